// round 13
// baseline (speedup 1.0000x reference)
#include <cuda_runtime.h>
#include <cuda_bf16.h>
#include <cstdint>

// Problem dims
#define B_  4
#define S_  4096
#define D_  2048
#define T_  1024
#define H_  16
#define HD_ 128
#define F_  8192
#define M_  (B_*T_)

// ---------------- device scratch ----------------
#define DEVBUF(type, name, count) __device__ __align__(256) type name[count]

DEVBUF(__nv_bfloat16, g_wqkv, 3LL*D_*D_);   // packed [wq|wk|wv]
DEVBUF(__nv_bfloat16, g_wo_b, D_*D_);
DEVBUF(__nv_bfloat16, g_w1_b, D_*F_);
DEVBUF(__nv_bfloat16, g_w3_b, D_*F_);
DEVBUF(__nv_bfloat16, g_w2_b, F_*D_);

DEVBUF(float, g_logits, B_*S_);
DEVBUF(int,   g_rankp,  4LL*B_*S_);
DEVBUF(int,   g_sel,    B_*T_);
DEVBUF(int,   g_pos,    B_*S_);
DEVBUF(float, g_rw,     B_*T_);

DEVBUF(__nv_bfloat16, g_h,   M_*D_);
DEVBUF(__nv_bfloat16, g_qb,  M_*D_);        // [b,h,t,hd] (rope'd)
DEVBUF(__nv_bfloat16, g_kb,  M_*D_);
DEVBUF(__nv_bfloat16, g_vb,  M_*D_);
DEVBUF(__nv_bfloat16, g_ob,  M_*D_);        // attn out [b,t,d] bf16
DEVBUF(float,         g_x1,  M_*D_);        // x_gathered + attn proj
DEVBUF(__nv_bfloat16, g_h2,  M_*D_);
DEVBUF(__nv_bfloat16, g_u,   M_*F_);        // bf16 u
DEVBUF(__nv_bfloat16, g_act, M_*F_);

// ---------------- PTX helpers ----------------
__device__ __forceinline__ uint32_t smem_u32(const void* p){
    uint32_t a;
    asm("{ .reg .u64 t; cvta.to.shared.u64 t, %1; cvt.u32.u64 %0, t; }" : "=r"(a) : "l"(p));
    return a;
}
__device__ __forceinline__ void cpasync16(uint32_t dst, const void* src){
    asm volatile("cp.async.cg.shared.global [%0], [%1], 16;" :: "r"(dst), "l"(src));
}
__device__ __forceinline__ void ldsm_x4(uint32_t* r, uint32_t addr){
    asm volatile("ldmatrix.sync.aligned.m8n8.x4.shared.b16 {%0,%1,%2,%3}, [%4];"
        : "=r"(r[0]), "=r"(r[1]), "=r"(r[2]), "=r"(r[3]) : "r"(addr));
}
__device__ __forceinline__ void ldsm_x4_t(uint32_t* r, uint32_t addr){
    asm volatile("ldmatrix.sync.aligned.m8n8.x4.trans.shared.b16 {%0,%1,%2,%3}, [%4];"
        : "=r"(r[0]), "=r"(r[1]), "=r"(r[2]), "=r"(r[3]) : "r"(addr));
}
__device__ __forceinline__ void mma16816(float* c, const uint32_t* a, uint32_t b0, uint32_t b1){
    asm volatile("mma.sync.aligned.m16n8k16.row.col.f32.bf16.bf16.f32 "
        "{%0,%1,%2,%3}, {%4,%5,%6,%7}, {%8,%9}, {%0,%1,%2,%3};"
        : "+f"(c[0]), "+f"(c[1]), "+f"(c[2]), "+f"(c[3])
        : "r"(a[0]), "r"(a[1]), "r"(a[2]), "r"(a[3]), "r"(b0), "r"(b1));
}
__device__ __forceinline__ uint32_t pack_bf16x2(float lo, float hi){
    __nv_bfloat162 v = __floats2bfloat162_rn(lo, hi);
    return *reinterpret_cast<uint32_t*>(&v);
}

// ---------------- raw mma.sync GEMM (128x128 CTA, 2 CTAs/SM) ----------------
// EPI=1: silu(Ubf)*acc -> bf16; EPI=2: bf16 store
// EPI=4: QKV+RoPE epilogue (z=0 q rope, z=1 k rope, z=2 v plain), Uv=freqs
// EPI=5: fused final: out[b,sel] = x + rw*(x1 + acc); Uv=x1, Xf=x, C=out
// EPI=6: x1 = x_gathered + acc; Xf=x, C=x1

#define BM 128
#define BN 128
#define BK 64
#define STAGE_B 32768
#define GEMM_SMEM (3*STAGE_B)

__device__ __forceinline__ void ldA_128x64(const __nv_bfloat16* g, int ld, uint32_t sbase, int tid){
    #pragma unroll
    for (int i = 0; i < 4; i++){
        int ch = tid + i*256;
        int r = ch >> 3, c = ch & 7;
        cpasync16(sbase + r*128 + (((c ^ (r & 7))) << 4),
                  (const char*)(g + (long long)r*ld) + c*16);
    }
}
__device__ __forceinline__ void ldB_64x128(const __nv_bfloat16* g, int ld, uint32_t sbase, int tid){
    #pragma unroll
    for (int i = 0; i < 4; i++){
        int ch = tid + i*256;
        int r = ch >> 4, c = ch & 15;
        int half = c >> 3, c8 = c & 7;
        cpasync16(sbase + r*256 + half*128 + ((c8 ^ (r & 7)) << 4),
                  (const char*)(g + (long long)r*ld) + c*16);
    }
}

template<int EPI>
__global__ void __launch_bounds__(256, 2) gemm3(
    const __nv_bfloat16* __restrict__ A, const __nv_bfloat16* __restrict__ Bm,
    float* __restrict__ C, int K, int lda, int ldb, int ldc,
    long long sA, long long sB, long long sC,
    const void* __restrict__ Uv, __nv_bfloat16* __restrict__ Obf,
    const float* __restrict__ Xf)
{
    extern __shared__ char smem[];
    uint32_t sb = smem_u32(smem);
    int tid = threadIdx.x, warp = tid >> 5, lane = tid & 31;
    int z = blockIdx.z;
    const __nv_bfloat16* Ab = A + (long long)z*sA + (long long)blockIdx.y*BM*lda;
    const __nv_bfloat16* Bb = Bm + (long long)z*sB;
    float* Cb = C ? C + (long long)z*sC : nullptr;
    __nv_bfloat16* Ob = Obf ? Obf + (long long)z*sC : nullptr;
    const int bn = blockIdx.x*BN;

    int wm = (warp & 3) * 32;
    int wn = (warp >> 2) * 64;

    float acc[2][8][4];
    #pragma unroll
    for (int i=0;i<2;i++)
        #pragma unroll
        for (int j=0;j<8;j++)
            #pragma unroll
            for (int e=0;e<4;e++) acc[i][j][e] = 0.f;

    const int NS = K >> 6;

    auto load_stage = [&](int s){
        uint32_t base = sb + (s % 3)*STAGE_B;
        int k0 = s*BK;
        ldA_128x64(Ab + k0, lda, base, tid);
        ldB_64x128(Bb + (long long)k0*ldb + bn, ldb, base + 16384, tid);
        asm volatile("cp.async.commit_group;" ::: "memory");
    };

    load_stage(0);
    if (NS > 1) load_stage(1);

    int a_row_lo = wm + ((lane >> 3) & 1)*8 + (lane & 7);
    int a_kq     = (lane >> 4) * 8;
    int b0_krow  = ((lane >> 3) & 1)*8 + (lane & 7);
    int b0_ncol  = wn + (lane >> 4)*8;

    for (int s = 0; s < NS; s++){
        if (s + 1 < NS) asm volatile("cp.async.wait_group 1;" ::: "memory");
        else            asm volatile("cp.async.wait_group 0;" ::: "memory");
        __syncthreads();

        if (s + 2 < NS) load_stage(s + 2);

        uint32_t Abase = sb + (s % 3)*STAGE_B;
        uint32_t Bbase = Abase + 16384;

        #pragma unroll
        for (int kk = 0; kk < BK; kk += 16){
            uint32_t af[2][4];
            #pragma unroll
            for (int ii = 0; ii < 2; ii++){
                int mrow = a_row_lo + ii*16;
                int kb = kk + a_kq;
                ldsm_x4(af[ii], Abase + mrow*128 + ((((kb >> 3) ^ (mrow & 7))) << 4));
            }
            uint32_t bfm[4][4];
            #pragma unroll
            for (int jj = 0; jj < 4; jj++){
                int krow = kk + b0_krow;
                int ncol = b0_ncol + jj*16;
                ldsm_x4_t(bfm[jj], Bbase + krow*256 + ((ncol >> 6) & 1)*128
                                 + ((((ncol >> 3) & 7) ^ (krow & 7)) << 4));
            }
            #pragma unroll
            for (int ii = 0; ii < 2; ii++)
                #pragma unroll
                for (int jj = 0; jj < 4; jj++){
                    mma16816(acc[ii][2*jj],   af[ii], bfm[jj][0], bfm[jj][1]);
                    mma16816(acc[ii][2*jj+1], af[ii], bfm[jj][2], bfm[jj][3]);
                }
        }
        __syncthreads();
    }

    if (EPI == 4){
        int h = blockIdx.x;
        if (z == 2){
            #pragma unroll
            for (int ii = 0; ii < 2; ii++){
                int r0 = blockIdx.y*BM + wm + ii*16 + (lane >> 2);
                int b = r0 >> 10, t = r0 & (T_-1);
                long long dbase = ((long long)(b*H_ + h)*T_ + t)*HD_;
                #pragma unroll
                for (int j8 = 0; j8 < 8; j8++){
                    int wc = wn + j8*8 + (lane & 3)*2;
                    *reinterpret_cast<uint32_t*>(g_vb + dbase + wc) =
                        pack_bf16x2(acc[ii][j8][0], acc[ii][j8][1]);
                    *reinterpret_cast<uint32_t*>(g_vb + dbase + 8LL*HD_ + wc) =
                        pack_bf16x2(acc[ii][j8][2], acc[ii][j8][3]);
                }
            }
        } else {
            float* sf = reinterpret_cast<float*>(smem);
            #pragma unroll
            for (int ii = 0; ii < 2; ii++){
                int sr = wm + ii*16 + (lane >> 2);
                #pragma unroll
                for (int j8 = 0; j8 < 8; j8++){
                    int sc = wn + j8*8 + (lane & 3)*2;
                    sf[sr*136 + sc]     = acc[ii][j8][0];
                    sf[sr*136 + sc + 1] = acc[ii][j8][1];
                    sf[(sr+8)*136 + sc]     = acc[ii][j8][2];
                    sf[(sr+8)*136 + sc + 1] = acc[ii][j8][3];
                }
            }
            __syncthreads();
            const float* fr = (const float*)Uv;
            __nv_bfloat16* dstp = (z == 0) ? g_qb : g_kb;
            #pragma unroll
            for (int i = 0; i < 32; i++){
                int idx = tid + i*256;
                int row = idx >> 6;
                int d2  = (idx & 63) * 2;
                int r = blockIdx.y*BM + row;
                int b = r >> 10, t = r & (T_-1);
                float v0 = sf[row*136 + d2];
                float v1 = sf[row*136 + d2 + 1];
                float p0 = sf[row*136 + (d2 ^ 64)];
                float p1 = sf[row*136 + (d2 ^ 64) + 1];
                int j0 = d2 & 63;
                float c0 = fr[(t*64 + j0)*2],     s0 = fr[(t*64 + j0)*2 + 1];
                float c1 = fr[(t*64 + j0 + 1)*2], s1 = fr[(t*64 + j0 + 1)*2 + 1];
                float o0, o1;
                if (d2 < 64){ o0 = v0*c0 - p0*s0; o1 = v1*c1 - p1*s1; }
                else        { o0 = p0*s0 + v0*c0; o1 = p1*s1 + v1*c1; }
                long long dst = ((long long)(b*H_ + h)*T_ + t)*HD_ + d2;
                *reinterpret_cast<uint32_t*>(dstp + dst) = pack_bf16x2(o0, o1);
            }
        }
        return;
    }

    #pragma unroll
    for (int ii = 0; ii < 2; ii++){
        int r0 = blockIdx.y*BM + wm + ii*16 + (lane >> 2);
        int selA = 0, selB = 0; float wA = 0.f, wB = 0.f; int bA = 0;
        if (EPI == 5 || EPI == 6){
            bA = r0 >> 10;
            selA = g_sel[r0];
            selB = g_sel[r0 + 8];
            if (EPI == 5){ wA = g_rw[r0]; wB = g_rw[r0 + 8]; }
        }
        #pragma unroll
        for (int j8 = 0; j8 < 8; j8++){
            int c0 = bn + wn + j8*8 + (lane & 3)*2;
            long long i0 = (long long)r0*ldc + c0;
            long long i1 = i0 + 8*(long long)ldc;
            if (EPI == 1){
                const __nv_bfloat16* Ub = (const __nv_bfloat16*)Uv;
                __nv_bfloat162 u0 = *reinterpret_cast<const __nv_bfloat162*>(Ub + i0);
                __nv_bfloat162 u1 = *reinterpret_cast<const __nv_bfloat162*>(Ub + i1);
                float ux = __bfloat162float(u0.x), uy = __bfloat162float(u0.y);
                float uz = __bfloat162float(u1.x), uw = __bfloat162float(u1.y);
                float s0 = __fdividef(ux, 1.f + __expf(-ux)) * acc[ii][j8][0];
                float s1 = __fdividef(uy, 1.f + __expf(-uy)) * acc[ii][j8][1];
                float s2 = __fdividef(uz, 1.f + __expf(-uz)) * acc[ii][j8][2];
                float s3 = __fdividef(uw, 1.f + __expf(-uw)) * acc[ii][j8][3];
                *reinterpret_cast<uint32_t*>(Ob + i0) = pack_bf16x2(s0, s1);
                *reinterpret_cast<uint32_t*>(Ob + i1) = pack_bf16x2(s2, s3);
            } else if (EPI == 2){
                *reinterpret_cast<uint32_t*>(Ob + i0) = pack_bf16x2(acc[ii][j8][0], acc[ii][j8][1]);
                *reinterpret_cast<uint32_t*>(Ob + i1) = pack_bf16x2(acc[ii][j8][2], acc[ii][j8][3]);
            } else if (EPI == 6){
                long long o0 = ((long long)bA*S_ + selA)*D_ + c0;
                long long o1 = ((long long)bA*S_ + selB)*D_ + c0;
                float2 x0 = *reinterpret_cast<const float2*>(Xf + o0);
                float2 x1v = *reinterpret_cast<const float2*>(Xf + o1);
                *reinterpret_cast<float2*>(Cb + i0) = make_float2(acc[ii][j8][0] + x0.x, acc[ii][j8][1] + x0.y);
                *reinterpret_cast<float2*>(Cb + i1) = make_float2(acc[ii][j8][2] + x1v.x, acc[ii][j8][3] + x1v.y);
            } else { // EPI == 5
                const float* X1 = (const float*)Uv;
                float2 a0 = *reinterpret_cast<const float2*>(X1 + i0);
                float2 a1 = *reinterpret_cast<const float2*>(X1 + i1);
                long long o0 = ((long long)bA*S_ + selA)*D_ + c0;
                long long o1 = ((long long)bA*S_ + selB)*D_ + c0;
                float2 x0 = *reinterpret_cast<const float2*>(Xf + o0);
                float2 x1v = *reinterpret_cast<const float2*>(Xf + o1);
                *reinterpret_cast<float2*>(Cb + o0) =
                    make_float2(x0.x + wA*(a0.x + acc[ii][j8][0]), x0.y + wA*(a0.y + acc[ii][j8][1]));
                *reinterpret_cast<float2*>(Cb + o1) =
                    make_float2(x1v.x + wB*(a1.x + acc[ii][j8][2]), x1v.y + wB*(a1.y + acc[ii][j8][3]));
            }
        }
    }
}

// ---------------- fused flash attention: double-buffered, 2 CTAs/SM ----------------
#define FA_STAGE 32768
#define FA_SMEM (32768 + 2*FA_STAGE)

__global__ void __launch_bounds__(256, 2) flash_kernel(
    const __nv_bfloat16* __restrict__ Q, const __nv_bfloat16* __restrict__ K,
    const __nv_bfloat16* __restrict__ V, __nv_bfloat16* __restrict__ Ob)
{
    extern __shared__ char smem[];
    uint32_t sq = smem_u32(smem);
    int tid = threadIdx.x, warp = tid >> 5, lane = tid & 31;
    int qt = blockIdx.x;
    int bh = blockIdx.y;
    int h = bh & (H_-1), b = bh >> 4;
    const __nv_bfloat16* Qb = Q + ((long long)bh*T_ + qt*128)*HD_;
    const __nv_bfloat16* Kb = K + (long long)bh*T_*HD_;
    const __nv_bfloat16* Vb = V + (long long)bh*T_*HD_;

    #pragma unroll
    for (int i = 0; i < 8; i++){
        int ch = tid + i*256;
        int r = ch >> 4, c = ch & 15;
        cpasync16(sq + r*256 + (c >> 3)*128 + (((c & 7) ^ (r & 7)) << 4),
                  (const char*)(Qb + (long long)r*HD_) + c*16);
    }
    auto load_kv = [&](int s){
        uint32_t base = sq + 32768 + (s & 1)*FA_STAGE;
        const __nv_bfloat16* Kt = Kb + (long long)s*64*HD_;
        const __nv_bfloat16* Vt = Vb + (long long)s*64*HD_;
        #pragma unroll
        for (int i = 0; i < 4; i++){
            int ch = tid + i*256;
            int r = ch >> 4, c = ch & 15;
            uint32_t off = r*256 + (c >> 3)*128 + (((c & 7) ^ (r & 7)) << 4);
            cpasync16(base + off,         (const char*)(Kt + (long long)r*HD_) + c*16);
            cpasync16(base + 16384 + off, (const char*)(Vt + (long long)r*HD_) + c*16);
        }
        asm volatile("cp.async.commit_group;" ::: "memory");
    };
    load_kv(0);
    load_kv(1);

    const int qr0 = warp*16;
    float o[16][4];
    #pragma unroll
    for (int j=0;j<16;j++)
        #pragma unroll
        for (int e=0;e<4;e++) o[j][e] = 0.f;
    float m0 = -1e30f, m1 = -1e30f, l0 = 0.f, l1 = 0.f;
    const float sc = 0.08838834764831845f;

    int a_row  = qr0 + ((lane >> 3) & 1)*8 + (lane & 7);
    int a_kq   = (lane >> 4) * 8;
    int b_row  = (lane >> 4)*8 + (lane & 7);
    int b_kq   = ((lane >> 3) & 1) * 8;
    int v_krow = ((lane >> 3) & 1)*8 + (lane & 7);
    int v_ncol = (lane >> 4) * 8;

    for (int s = 0; s < 16; s++){
        if (s + 1 < 16) asm volatile("cp.async.wait_group 1;" ::: "memory");
        else            asm volatile("cp.async.wait_group 0;" ::: "memory");
        __syncthreads();

        uint32_t Kbase = sq + 32768 + (s & 1)*FA_STAGE;
        uint32_t Vbase = Kbase + 16384;

        float sv[8][4];
        #pragma unroll
        for (int j=0;j<8;j++)
            #pragma unroll
            for (int e=0;e<4;e++) sv[j][e] = 0.f;

        #pragma unroll
        for (int kk = 0; kk < 8; kk++){
            uint32_t af[4];
            int cA = (kk*16 + a_kq) >> 3;
            ldsm_x4(af, sq + a_row*256 + (cA >> 3)*128 + (((cA & 7) ^ (a_row & 7)) << 4));
            #pragma unroll
            for (int jj = 0; jj < 4; jj++){
                uint32_t bfm[4];
                int nrow = jj*16 + b_row;
                int cB = (kk*16 + b_kq) >> 3;
                ldsm_x4(bfm, Kbase + nrow*256 + (cB >> 3)*128 + (((cB & 7) ^ (nrow & 7)) << 4));
                mma16816(sv[2*jj],   af, bfm[0], bfm[1]);
                mma16816(sv[2*jj+1], af, bfm[2], bfm[3]);
            }
        }

        float rm0 = -1e30f, rm1 = -1e30f;
        #pragma unroll
        for (int j=0;j<8;j++){
            sv[j][0] *= sc; sv[j][1] *= sc; sv[j][2] *= sc; sv[j][3] *= sc;
            rm0 = fmaxf(rm0, fmaxf(sv[j][0], sv[j][1]));
            rm1 = fmaxf(rm1, fmaxf(sv[j][2], sv[j][3]));
        }
        rm0 = fmaxf(rm0, __shfl_xor_sync(0xffffffffu, rm0, 1));
        rm0 = fmaxf(rm0, __shfl_xor_sync(0xffffffffu, rm0, 2));
        rm1 = fmaxf(rm1, __shfl_xor_sync(0xffffffffu, rm1, 1));
        rm1 = fmaxf(rm1, __shfl_xor_sync(0xffffffffu, rm1, 2));
        float mn0 = fmaxf(m0, rm0), mn1 = fmaxf(m1, rm1);
        float rs0 = 0.f, rs1 = 0.f;
        #pragma unroll
        for (int j=0;j<8;j++){
            sv[j][0] = __expf(sv[j][0] - mn0);
            sv[j][1] = __expf(sv[j][1] - mn0);
            sv[j][2] = __expf(sv[j][2] - mn1);
            sv[j][3] = __expf(sv[j][3] - mn1);
            rs0 += sv[j][0] + sv[j][1];
            rs1 += sv[j][2] + sv[j][3];
        }
        rs0 += __shfl_xor_sync(0xffffffffu, rs0, 1);
        rs0 += __shfl_xor_sync(0xffffffffu, rs0, 2);
        rs1 += __shfl_xor_sync(0xffffffffu, rs1, 1);
        rs1 += __shfl_xor_sync(0xffffffffu, rs1, 2);
        float c0 = __expf(m0 - mn0), c1 = __expf(m1 - mn1);
        l0 = l0*c0 + rs0;  l1 = l1*c1 + rs1;
        m0 = mn0;  m1 = mn1;
        #pragma unroll
        for (int j=0;j<16;j++){
            o[j][0] *= c0; o[j][1] *= c0; o[j][2] *= c1; o[j][3] *= c1;
        }

        #pragma unroll
        for (int k2 = 0; k2 < 4; k2++){
            uint32_t pa[4];
            pa[0] = pack_bf16x2(sv[2*k2][0],   sv[2*k2][1]);
            pa[1] = pack_bf16x2(sv[2*k2][2],   sv[2*k2][3]);
            pa[2] = pack_bf16x2(sv[2*k2+1][0], sv[2*k2+1][1]);
            pa[3] = pack_bf16x2(sv[2*k2+1][2], sv[2*k2+1][3]);
            int krow = k2*16 + v_krow;
            #pragma unroll
            for (int jj = 0; jj < 8; jj++){
                uint32_t bv[4];
                int ncol = jj*16 + v_ncol;
                ldsm_x4_t(bv, Vbase + krow*256 + ((ncol >> 6) & 1)*128
                              + ((((ncol >> 3) & 7) ^ (krow & 7)) << 4));
                mma16816(o[2*jj],   pa, bv[0], bv[1]);
                mma16816(o[2*jj+1], pa, bv[2], bv[3]);
            }
        }
        __syncthreads();
        if (s + 2 < 16) load_kv(s + 2);
    }

    float il0 = __frcp_rn(l0), il1 = __frcp_rn(l1);
    int t0 = qt*128 + qr0 + (lane >> 2);
    long long base0 = ((long long)b*T_ + t0)*D_ + h*HD_;
    long long base1 = base0 + 8LL*D_;
    #pragma unroll
    for (int j=0;j<16;j++){
        int col = j*8 + (lane & 3)*2;
        *reinterpret_cast<uint32_t*>(Ob + base0 + col) = pack_bf16x2(o[j][0]*il0, o[j][1]*il0);
        *reinterpret_cast<uint32_t*>(Ob + base1 + col) = pack_bf16x2(o[j][2]*il1, o[j][3]*il1);
    }
}

// ---------------- elementwise / reduction kernels ----------------

__global__ void cvt_qkv_kernel(const float* __restrict__ wq, const float* __restrict__ wk,
                               const float* __restrict__ wv){
    const int SEG = 1 << 20;
    for (int i = blockIdx.x*blockDim.x + threadIdx.x; i < 3*SEG; i += gridDim.x*blockDim.x){
        int seg = i >> 20;
        long long off = i & (SEG-1);
        const float* src = (seg == 0) ? wq : (seg == 1) ? wk : wv;
        __nv_bfloat16* dst = g_wqkv + (long long)seg*D_*D_;
        float4 v = reinterpret_cast<const float4*>(src)[off];
        __nv_bfloat162* o = reinterpret_cast<__nv_bfloat162*>(dst) + off*2;
        o[0] = __floats2bfloat162_rn(v.x, v.y);
        o[1] = __floats2bfloat162_rn(v.z, v.w);
    }
}

__global__ void cvt_rest_kernel(const float* __restrict__ wo, const float* __restrict__ w1,
                                const float* __restrict__ w3, const float* __restrict__ w2){
    const int SEG = 1 << 20;
    for (long long i = blockIdx.x*(long long)blockDim.x + threadIdx.x;
         i < 13LL*SEG; i += (long long)gridDim.x*blockDim.x){
        int seg = (int)(i >> 20);
        const float* src; __nv_bfloat16* dst; long long off;
        if (seg < 1){        off = i;            src = wo; dst = g_wo_b; }
        else if (seg < 5){   off = i - 1LL*SEG;  src = w1; dst = g_w1_b; }
        else if (seg < 9){   off = i - 5LL*SEG;  src = w3; dst = g_w3_b; }
        else{                off = i - 9LL*SEG;  src = w2; dst = g_w2_b; }
        float4 v = reinterpret_cast<const float4*>(src)[off];
        __nv_bfloat162* o = reinterpret_cast<__nv_bfloat162*>(dst) + off*2;
        o[0] = __floats2bfloat162_rn(v.x, v.y);
        o[1] = __floats2bfloat162_rn(v.z, v.w);
    }
}

__global__ void __launch_bounds__(256) router_kernel(const float* __restrict__ x,
                                                     const float* __restrict__ wr){
    int row = blockIdx.x*8 + (threadIdx.x >> 5);
    int lane = threadIdx.x & 31;
    const float* xr = x + (long long)row * D_;
    float s = 0.f;
    #pragma unroll 8
    for (int i = lane; i < D_; i += 32) s += xr[i] * wr[i];
    #pragma unroll
    for (int o=16;o;o>>=1) s += __shfl_xor_sync(0xffffffffu, s, o);
    if (!lane) g_logits[row] = s;
}

// chunked exact rank counting: grid (16, 4, B), partial ranks, no atomics
__global__ void __launch_bounds__(256) rank_kernel(){
    __shared__ float sv[1024];
    int b = blockIdx.z, c = blockIdx.y;
    int i = blockIdx.x*256 + threadIdx.x;
    for (int j = threadIdx.x; j < 1024; j += 256) sv[j] = g_logits[b*S_ + c*1024 + j];
    __syncthreads();
    float v = g_logits[b*S_ + i];
    int base = c*1024;
    int rank = 0;
    #pragma unroll 8
    for (int j = 0; j < 1024; j++){
        float vj = sv[j];
        rank += (vj > v) || (vj == v && (base + j) < i);
    }
    g_rankp[((long long)c*B_ + b)*S_ + i] = rank;
}

// compaction + router softmax
__global__ void __launch_bounds__(1024) compact_kernel(){
    __shared__ int   scn[1024];
    __shared__ float selv[T_];
    __shared__ float red[1024];
    int b = blockIdx.x, tid = threadIdx.x;
    int base_i = tid*4;
    float v[4]; int rank[4];
    #pragma unroll
    for (int e=0;e<4;e++){
        int i = base_i + e;
        v[e] = g_logits[b*S_ + i];
        int r = 0;
        #pragma unroll
        for (int c=0;c<4;c++) r += g_rankp[((long long)c*B_ + b)*S_ + i];
        rank[e] = r;
    }
    int flag[4]; int cnt = 0;
    #pragma unroll
    for (int e=0;e<4;e++){ flag[e] = rank[e] < T_; cnt += flag[e]; }
    scn[tid] = cnt; __syncthreads();
    for (int off=1; off<1024; off<<=1){
        int t = 0;
        if (tid >= off) t = scn[tid-off];
        __syncthreads();
        scn[tid] += t;
        __syncthreads();
    }
    int pos = scn[tid] - cnt;
    #pragma unroll
    for (int e=0;e<4;e++){
        int i = base_i + e;
        int p = -1;
        if (flag[e]){ p = pos++; g_sel[b*T_+p] = i; selv[p] = v[e]; }
        g_pos[b*S_ + i] = p;
    }
    __syncthreads();
    float sval = selv[tid];
    red[tid] = sval; __syncthreads();
    for (int off=512; off; off>>=1){ if (tid < off) red[tid] = fmaxf(red[tid], red[tid+off]); __syncthreads(); }
    float mx = red[0]; __syncthreads();
    float ex = __expf(sval - mx);
    red[tid] = ex; __syncthreads();
    for (int off=512; off; off>>=1){ if (tid < off) red[tid] += red[tid+off]; __syncthreads(); }
    g_rw[b*T_ + tid] = ex / red[0];
}

__device__ __forceinline__ float block_sum_256(float v, float* sh){
    #pragma unroll
    for (int o=16;o;o>>=1) v += __shfl_xor_sync(0xffffffffu, v, o);
    if ((threadIdx.x & 31) == 0) sh[threadIdx.x >> 5] = v;
    __syncthreads();
    if (threadIdx.x == 0){ float t=0; for (int w=0;w<8;w++) t += sh[w]; sh[0] = t; }
    __syncthreads();
    float r = sh[0];
    __syncthreads();
    return r;
}

__global__ void __launch_bounds__(256) gather_rms_kernel(const float* __restrict__ x,
                                                         const float* __restrict__ g1){
    __shared__ float sh[8];
    int bt = blockIdx.x;
    int b = bt >> 10;
    int s = g_sel[bt];
    const float* xr = x + ((long long)b*S_ + s) * D_;
    float vals[8]; float ss = 0.f;
    #pragma unroll
    for (int e=0;e<8;e++){ float val = xr[threadIdx.x + e*256]; vals[e] = val; ss += val*val; }
    float tot = block_sum_256(ss, sh);
    float inv = rsqrtf(tot / D_ + 1e-6f);
    long long base = (long long)bt * D_;
    #pragma unroll
    for (int e=0;e<8;e++){
        int d = threadIdx.x + e*256;
        g_h[base+d] = __float2bfloat16(vals[e] * inv * g1[d]);
    }
}

__global__ void __launch_bounds__(256) resid_rms_kernel(const float* __restrict__ g2){
    __shared__ float sh[8];
    long long base = (long long)blockIdx.x * D_;
    float vals[8]; float ss = 0.f;
    #pragma unroll
    for (int e=0;e<8;e++){
        int d = threadIdx.x + e*256;
        float val = g_x1[base+d];
        vals[e] = val; ss += val*val;
    }
    float tot = block_sum_256(ss, sh);
    float inv = rsqrtf(tot / D_ + 1e-6f);
    #pragma unroll
    for (int e=0;e<8;e++){
        int d = threadIdx.x + e*256;
        g_h2[base+d] = __float2bfloat16(vals[e] * inv * g2[d]);
    }
}

__global__ void __launch_bounds__(256) final_copy_kernel(const float* __restrict__ x,
                                                         float* __restrict__ out){
    int bs = blockIdx.x;
    if (g_pos[bs] >= 0) return;
    long long rb = (long long)bs * D_;
    #pragma unroll
    for (int e=0;e<2;e++){
        int i = threadIdx.x + e*256;
        reinterpret_cast<float4*>(out + rb)[i] =
            reinterpret_cast<const float4*>(x + rb)[i];
    }
}

// ---------------- host orchestration ----------------
#define GETP(sym_) ([&]{ void* p_ = nullptr; cudaGetSymbolAddress(&p_, sym_); return p_; }())

extern "C" void kernel_launch(void* const* d_in, const int* in_sizes, int n_in,
                              void* d_out, int out_size)
{
    const float* x     = (const float*)d_in[0];
    const float* freqs = (const float*)d_in[2];
    const float* wr    = (const float*)d_in[3];
    const float* g1    = (const float*)d_in[4];
    const float* wq    = (const float*)d_in[5];
    const float* wk    = (const float*)d_in[6];
    const float* wv    = (const float*)d_in[7];
    const float* wo    = (const float*)d_in[8];
    const float* g2    = (const float*)d_in[9];
    const float* w1    = (const float*)d_in[10];
    const float* w3    = (const float*)d_in[11];
    const float* w2    = (const float*)d_in[12];
    float* out = (float*)d_out;

    static bool init_done = false;
    static cudaStream_t s2, s3;
    static cudaEvent_t ev_fork, ev_join, ev_router;
    if (!init_done){
        cudaFuncSetAttribute(gemm3<1>, cudaFuncAttributeMaxDynamicSharedMemorySize, GEMM_SMEM);
        cudaFuncSetAttribute(gemm3<2>, cudaFuncAttributeMaxDynamicSharedMemorySize, GEMM_SMEM);
        cudaFuncSetAttribute(gemm3<4>, cudaFuncAttributeMaxDynamicSharedMemorySize, GEMM_SMEM);
        cudaFuncSetAttribute(gemm3<5>, cudaFuncAttributeMaxDynamicSharedMemorySize, GEMM_SMEM);
        cudaFuncSetAttribute(gemm3<6>, cudaFuncAttributeMaxDynamicSharedMemorySize, GEMM_SMEM);
        cudaFuncSetAttribute(flash_kernel, cudaFuncAttributeMaxDynamicSharedMemorySize, FA_SMEM);
        cudaStreamCreateWithFlags(&s2, cudaStreamNonBlocking);
        cudaStreamCreateWithFlags(&s3, cudaStreamNonBlocking);
        cudaEventCreateWithFlags(&ev_fork,   cudaEventDisableTiming);
        cudaEventCreateWithFlags(&ev_join,   cudaEventDisableTiming);
        cudaEventCreateWithFlags(&ev_router, cudaEventDisableTiming);
        init_done = true;
    }

    __nv_bfloat16* p_wqkv = (__nv_bfloat16*)GETP(g_wqkv);
    __nv_bfloat16* p_wo = (__nv_bfloat16*)GETP(g_wo_b);
    __nv_bfloat16* p_w1 = (__nv_bfloat16*)GETP(g_w1_b);
    __nv_bfloat16* p_w3 = (__nv_bfloat16*)GETP(g_w3_b);
    __nv_bfloat16* p_w2 = (__nv_bfloat16*)GETP(g_w2_b);
    __nv_bfloat16* p_h  = (__nv_bfloat16*)GETP(g_h);
    __nv_bfloat16* p_qb = (__nv_bfloat16*)GETP(g_qb);
    __nv_bfloat16* p_kb = (__nv_bfloat16*)GETP(g_kb);
    __nv_bfloat16* p_vb = (__nv_bfloat16*)GETP(g_vb);
    __nv_bfloat16* p_ob = (__nv_bfloat16*)GETP(g_ob);
    __nv_bfloat16* p_h2 = (__nv_bfloat16*)GETP(g_h2);
    __nv_bfloat16* p_u  = (__nv_bfloat16*)GETP(g_u);
    __nv_bfloat16* p_ac = (__nv_bfloat16*)GETP(g_act);
    float* p_x1 = (float*)GETP(g_x1);

    // fork: s2 converts wo|w1|w3|w2 ; s3 runs the router chain (independent of weights)
    cudaEventRecord(ev_fork, 0);
    cudaStreamWaitEvent(s2, ev_fork, 0);
    cudaStreamWaitEvent(s3, ev_fork, 0);

    cvt_rest_kernel<<<4096, 256, 0, s2>>>(wo, w1, w3, w2);
    cudaEventRecord(ev_join, s2);

    router_kernel<<<B_*S_/8, 256, 0, s3>>>(x, wr);
    rank_kernel<<<dim3(16, 4, B_), 256, 0, s3>>>();
    compact_kernel<<<B_, 1024, 0, s3>>>();
    gather_rms_kernel<<<M_, 256, 0, s3>>>(x, g1);
    cudaEventRecord(ev_router, s3);

    // main chain: QKV weight conversion overlaps router chain
    cvt_qkv_kernel<<<2048, 256>>>(wq, wk, wv);
    cudaStreamWaitEvent(0, ev_router, 0);

    // QKV GEMM with fused RoPE epilogue
    gemm3<4><<<dim3(D_/BN, M_/BM, 3), 256, GEMM_SMEM>>>(p_h, p_wqkv, nullptr,
        D_, D_, D_, D_, 0, (long long)D_*D_, 0, freqs, nullptr, nullptr);

    // fused flash attention -> g_ob [b,t,d] bf16
    flash_kernel<<<dim3(T_/128, B_*H_), 256, FA_SMEM>>>(p_qb, p_kb, p_vb, p_ob);

    // join: wo/w1/w3/w2 must be converted from here on
    cudaStreamWaitEvent(0, ev_join, 0);

    // attn projection + gathered residual: x1 = x[b,sel] + ob@wo
    gemm3<6><<<dim3(D_/BN, M_/BM, 1), 256, GEMM_SMEM>>>(p_ob, p_wo, p_x1,
        D_, D_, D_, D_, 0,0,0, nullptr, nullptr, x);

    // rmsnorm2
    resid_rms_kernel<<<M_, 256>>>(g2);

    // FFN: u = h2@w1 (bf16) ; act = silu(u)*(h2@w3)
    gemm3<2><<<dim3(F_/BN, M_/BM, 1), 256, GEMM_SMEM>>>(p_h2, p_w1, nullptr,
        D_, D_, F_, F_, 0,0,0, nullptr, p_u, nullptr);
    gemm3<1><<<dim3(F_/BN, M_/BM, 1), 256, GEMM_SMEM>>>(p_h2, p_w3, nullptr,
        D_, D_, F_, F_, 0,0,0, p_u, p_ac, nullptr);

    // w2 GEMM with fused final scatter-add
    gemm3<5><<<dim3(D_/BN, M_/BM, 1), 256, GEMM_SMEM>>>(p_ac, p_w2, out,
        F_, F_, D_, D_, 0,0,0, p_x1, nullptr, x);

    // copy non-selected rows
    final_copy_kernel<<<B_*S_, 256>>>(x, out);
}

// round 14
// speedup vs baseline: 1.5126x; 1.5126x over previous
#include <cuda_runtime.h>
#include <cuda_bf16.h>
#include <cstdint>

// Problem dims
#define B_  4
#define S_  4096
#define D_  2048
#define T_  1024
#define H_  16
#define HD_ 128
#define F_  8192
#define M_  (B_*T_)

// ---------------- device scratch ----------------
#define DEVBUF(type, name, count) __device__ __align__(256) type name[count]

DEVBUF(__nv_bfloat16, g_wqkv, 3LL*D_*D_);   // packed [wq|wk|wv]
DEVBUF(__nv_bfloat16, g_wo_b, D_*D_);
DEVBUF(__nv_bfloat16, g_w1_b, D_*F_);
DEVBUF(__nv_bfloat16, g_w3_b, D_*F_);
DEVBUF(__nv_bfloat16, g_w2_b, F_*D_);

DEVBUF(float, g_logits, B_*S_);
DEVBUF(int,   g_rankp,  4LL*B_*S_);
DEVBUF(int,   g_sel,    B_*T_);
DEVBUF(int,   g_pos,    B_*S_);
DEVBUF(float, g_rw,     B_*T_);

DEVBUF(__nv_bfloat16, g_h,   M_*D_);
DEVBUF(__nv_bfloat16, g_qb,  M_*D_);        // [b,h,t,hd] (rope'd)
DEVBUF(__nv_bfloat16, g_kb,  M_*D_);
DEVBUF(__nv_bfloat16, g_vb,  M_*D_);
DEVBUF(__nv_bfloat16, g_ob,  M_*D_);        // attn out [b,t,d] bf16
DEVBUF(float,         g_x1,  M_*D_);        // x_gathered + attn proj
DEVBUF(__nv_bfloat16, g_h2,  M_*D_);
DEVBUF(__nv_bfloat16, g_u,   M_*F_);        // bf16 u
DEVBUF(__nv_bfloat16, g_act, M_*F_);

// ---------------- PTX helpers ----------------
__device__ __forceinline__ uint32_t smem_u32(const void* p){
    uint32_t a;
    asm("{ .reg .u64 t; cvta.to.shared.u64 t, %1; cvt.u32.u64 %0, t; }" : "=r"(a) : "l"(p));
    return a;
}
__device__ __forceinline__ void cpasync16(uint32_t dst, const void* src){
    asm volatile("cp.async.cg.shared.global [%0], [%1], 16;" :: "r"(dst), "l"(src));
}
__device__ __forceinline__ void ldsm_x4(uint32_t* r, uint32_t addr){
    asm volatile("ldmatrix.sync.aligned.m8n8.x4.shared.b16 {%0,%1,%2,%3}, [%4];"
        : "=r"(r[0]), "=r"(r[1]), "=r"(r[2]), "=r"(r[3]) : "r"(addr));
}
__device__ __forceinline__ void ldsm_x4_t(uint32_t* r, uint32_t addr){
    asm volatile("ldmatrix.sync.aligned.m8n8.x4.trans.shared.b16 {%0,%1,%2,%3}, [%4];"
        : "=r"(r[0]), "=r"(r[1]), "=r"(r[2]), "=r"(r[3]) : "r"(addr));
}
__device__ __forceinline__ void mma16816(float* c, const uint32_t* a, uint32_t b0, uint32_t b1){
    asm volatile("mma.sync.aligned.m16n8k16.row.col.f32.bf16.bf16.f32 "
        "{%0,%1,%2,%3}, {%4,%5,%6,%7}, {%8,%9}, {%0,%1,%2,%3};"
        : "+f"(c[0]), "+f"(c[1]), "+f"(c[2]), "+f"(c[3])
        : "r"(a[0]), "r"(a[1]), "r"(a[2]), "r"(a[3]), "r"(b0), "r"(b1));
}
__device__ __forceinline__ uint32_t pack_bf16x2(float lo, float hi){
    __nv_bfloat162 v = __floats2bfloat162_rn(lo, hi);
    return *reinterpret_cast<uint32_t*>(&v);
}

// ---------------- raw mma.sync GEMM (128x128 CTA, 2 CTAs/SM) ----------------
// EPI=1: silu(Ubf)*acc -> bf16; EPI=2: bf16 store
// EPI=4: QKV+RoPE epilogue (z=0 q rope, z=1 k rope, z=2 v plain), Uv=freqs
// EPI=5: fused final: out[b,sel] = x + rw*(x1 + acc); Uv=x1, Xf=x, C=out
// EPI=6: x1 = x_gathered + acc; Xf=x, C=x1

#define BM 128
#define BN 128
#define BK 64
#define STAGE_B 32768
#define GEMM_SMEM (3*STAGE_B)

__device__ __forceinline__ void ldA_128x64(const __nv_bfloat16* g, int ld, uint32_t sbase, int tid){
    #pragma unroll
    for (int i = 0; i < 4; i++){
        int ch = tid + i*256;
        int r = ch >> 3, c = ch & 7;
        cpasync16(sbase + r*128 + (((c ^ (r & 7))) << 4),
                  (const char*)(g + (long long)r*ld) + c*16);
    }
}
__device__ __forceinline__ void ldB_64x128(const __nv_bfloat16* g, int ld, uint32_t sbase, int tid){
    #pragma unroll
    for (int i = 0; i < 4; i++){
        int ch = tid + i*256;
        int r = ch >> 4, c = ch & 15;
        int half = c >> 3, c8 = c & 7;
        cpasync16(sbase + r*256 + half*128 + ((c8 ^ (r & 7)) << 4),
                  (const char*)(g + (long long)r*ld) + c*16);
    }
}

template<int EPI>
__global__ void __launch_bounds__(256, 2) gemm3(
    const __nv_bfloat16* __restrict__ A, const __nv_bfloat16* __restrict__ Bm,
    float* __restrict__ C, int K, int lda, int ldb, int ldc,
    long long sA, long long sB, long long sC,
    const void* __restrict__ Uv, __nv_bfloat16* __restrict__ Obf,
    const float* __restrict__ Xf)
{
    extern __shared__ char smem[];
    uint32_t sb = smem_u32(smem);
    int tid = threadIdx.x, warp = tid >> 5, lane = tid & 31;
    int z = blockIdx.z;
    const __nv_bfloat16* Ab = A + (long long)z*sA + (long long)blockIdx.y*BM*lda;
    const __nv_bfloat16* Bb = Bm + (long long)z*sB;
    float* Cb = C ? C + (long long)z*sC : nullptr;
    __nv_bfloat16* Ob = Obf ? Obf + (long long)z*sC : nullptr;
    const int bn = blockIdx.x*BN;

    int wm = (warp & 3) * 32;
    int wn = (warp >> 2) * 64;

    float acc[2][8][4];
    #pragma unroll
    for (int i=0;i<2;i++)
        #pragma unroll
        for (int j=0;j<8;j++)
            #pragma unroll
            for (int e=0;e<4;e++) acc[i][j][e] = 0.f;

    const int NS = K >> 6;

    auto load_stage = [&](int s){
        uint32_t base = sb + (s % 3)*STAGE_B;
        int k0 = s*BK;
        ldA_128x64(Ab + k0, lda, base, tid);
        ldB_64x128(Bb + (long long)k0*ldb + bn, ldb, base + 16384, tid);
        asm volatile("cp.async.commit_group;" ::: "memory");
    };

    load_stage(0);
    if (NS > 1) load_stage(1);

    int a_row_lo = wm + ((lane >> 3) & 1)*8 + (lane & 7);
    int a_kq     = (lane >> 4) * 8;
    int b0_krow  = ((lane >> 3) & 1)*8 + (lane & 7);
    int b0_ncol  = wn + (lane >> 4)*8;

    for (int s = 0; s < NS; s++){
        if (s + 1 < NS) asm volatile("cp.async.wait_group 1;" ::: "memory");
        else            asm volatile("cp.async.wait_group 0;" ::: "memory");
        __syncthreads();

        if (s + 2 < NS) load_stage(s + 2);

        uint32_t Abase = sb + (s % 3)*STAGE_B;
        uint32_t Bbase = Abase + 16384;

        #pragma unroll
        for (int kk = 0; kk < BK; kk += 16){
            uint32_t af[2][4];
            #pragma unroll
            for (int ii = 0; ii < 2; ii++){
                int mrow = a_row_lo + ii*16;
                int kb = kk + a_kq;
                ldsm_x4(af[ii], Abase + mrow*128 + ((((kb >> 3) ^ (mrow & 7))) << 4));
            }
            uint32_t bfm[4][4];
            #pragma unroll
            for (int jj = 0; jj < 4; jj++){
                int krow = kk + b0_krow;
                int ncol = b0_ncol + jj*16;
                ldsm_x4_t(bfm[jj], Bbase + krow*256 + ((ncol >> 6) & 1)*128
                                 + ((((ncol >> 3) & 7) ^ (krow & 7)) << 4));
            }
            #pragma unroll
            for (int ii = 0; ii < 2; ii++)
                #pragma unroll
                for (int jj = 0; jj < 4; jj++){
                    mma16816(acc[ii][2*jj],   af[ii], bfm[jj][0], bfm[jj][1]);
                    mma16816(acc[ii][2*jj+1], af[ii], bfm[jj][2], bfm[jj][3]);
                }
        }
        __syncthreads();
    }

    if (EPI == 4){
        int h = blockIdx.x;
        if (z == 2){
            #pragma unroll
            for (int ii = 0; ii < 2; ii++){
                int r0 = blockIdx.y*BM + wm + ii*16 + (lane >> 2);
                int b = r0 >> 10, t = r0 & (T_-1);
                long long dbase = ((long long)(b*H_ + h)*T_ + t)*HD_;
                #pragma unroll
                for (int j8 = 0; j8 < 8; j8++){
                    int wc = wn + j8*8 + (lane & 3)*2;
                    *reinterpret_cast<uint32_t*>(g_vb + dbase + wc) =
                        pack_bf16x2(acc[ii][j8][0], acc[ii][j8][1]);
                    *reinterpret_cast<uint32_t*>(g_vb + dbase + 8LL*HD_ + wc) =
                        pack_bf16x2(acc[ii][j8][2], acc[ii][j8][3]);
                }
            }
        } else {
            float* sf = reinterpret_cast<float*>(smem);
            #pragma unroll
            for (int ii = 0; ii < 2; ii++){
                int sr = wm + ii*16 + (lane >> 2);
                #pragma unroll
                for (int j8 = 0; j8 < 8; j8++){
                    int sc = wn + j8*8 + (lane & 3)*2;
                    sf[sr*136 + sc]     = acc[ii][j8][0];
                    sf[sr*136 + sc + 1] = acc[ii][j8][1];
                    sf[(sr+8)*136 + sc]     = acc[ii][j8][2];
                    sf[(sr+8)*136 + sc + 1] = acc[ii][j8][3];
                }
            }
            __syncthreads();
            const float* fr = (const float*)Uv;
            __nv_bfloat16* dstp = (z == 0) ? g_qb : g_kb;
            #pragma unroll
            for (int i = 0; i < 32; i++){
                int idx = tid + i*256;
                int row = idx >> 6;
                int d2  = (idx & 63) * 2;
                int r = blockIdx.y*BM + row;
                int b = r >> 10, t = r & (T_-1);
                float v0 = sf[row*136 + d2];
                float v1 = sf[row*136 + d2 + 1];
                float p0 = sf[row*136 + (d2 ^ 64)];
                float p1 = sf[row*136 + (d2 ^ 64) + 1];
                int j0 = d2 & 63;
                float c0 = fr[(t*64 + j0)*2],     s0 = fr[(t*64 + j0)*2 + 1];
                float c1 = fr[(t*64 + j0 + 1)*2], s1 = fr[(t*64 + j0 + 1)*2 + 1];
                float o0, o1;
                if (d2 < 64){ o0 = v0*c0 - p0*s0; o1 = v1*c1 - p1*s1; }
                else        { o0 = p0*s0 + v0*c0; o1 = p1*s1 + v1*c1; }
                long long dst = ((long long)(b*H_ + h)*T_ + t)*HD_ + d2;
                *reinterpret_cast<uint32_t*>(dstp + dst) = pack_bf16x2(o0, o1);
            }
        }
        return;
    }

    #pragma unroll
    for (int ii = 0; ii < 2; ii++){
        int r0 = blockIdx.y*BM + wm + ii*16 + (lane >> 2);
        int selA = 0, selB = 0; float wA = 0.f, wB = 0.f; int bA = 0;
        if (EPI == 5 || EPI == 6){
            bA = r0 >> 10;
            selA = g_sel[r0];
            selB = g_sel[r0 + 8];
            if (EPI == 5){ wA = g_rw[r0]; wB = g_rw[r0 + 8]; }
        }
        #pragma unroll
        for (int j8 = 0; j8 < 8; j8++){
            int c0 = bn + wn + j8*8 + (lane & 3)*2;
            long long i0 = (long long)r0*ldc + c0;
            long long i1 = i0 + 8*(long long)ldc;
            if (EPI == 1){
                const __nv_bfloat16* Ub = (const __nv_bfloat16*)Uv;
                __nv_bfloat162 u0 = *reinterpret_cast<const __nv_bfloat162*>(Ub + i0);
                __nv_bfloat162 u1 = *reinterpret_cast<const __nv_bfloat162*>(Ub + i1);
                float ux = __bfloat162float(u0.x), uy = __bfloat162float(u0.y);
                float uz = __bfloat162float(u1.x), uw = __bfloat162float(u1.y);
                float s0 = __fdividef(ux, 1.f + __expf(-ux)) * acc[ii][j8][0];
                float s1 = __fdividef(uy, 1.f + __expf(-uy)) * acc[ii][j8][1];
                float s2 = __fdividef(uz, 1.f + __expf(-uz)) * acc[ii][j8][2];
                float s3 = __fdividef(uw, 1.f + __expf(-uw)) * acc[ii][j8][3];
                *reinterpret_cast<uint32_t*>(Ob + i0) = pack_bf16x2(s0, s1);
                *reinterpret_cast<uint32_t*>(Ob + i1) = pack_bf16x2(s2, s3);
            } else if (EPI == 2){
                *reinterpret_cast<uint32_t*>(Ob + i0) = pack_bf16x2(acc[ii][j8][0], acc[ii][j8][1]);
                *reinterpret_cast<uint32_t*>(Ob + i1) = pack_bf16x2(acc[ii][j8][2], acc[ii][j8][3]);
            } else if (EPI == 6){
                long long o0 = ((long long)bA*S_ + selA)*D_ + c0;
                long long o1 = ((long long)bA*S_ + selB)*D_ + c0;
                float2 x0 = *reinterpret_cast<const float2*>(Xf + o0);
                float2 x1v = *reinterpret_cast<const float2*>(Xf + o1);
                *reinterpret_cast<float2*>(Cb + i0) = make_float2(acc[ii][j8][0] + x0.x, acc[ii][j8][1] + x0.y);
                *reinterpret_cast<float2*>(Cb + i1) = make_float2(acc[ii][j8][2] + x1v.x, acc[ii][j8][3] + x1v.y);
            } else { // EPI == 5
                const float* X1 = (const float*)Uv;
                float2 a0 = *reinterpret_cast<const float2*>(X1 + i0);
                float2 a1 = *reinterpret_cast<const float2*>(X1 + i1);
                long long o0 = ((long long)bA*S_ + selA)*D_ + c0;
                long long o1 = ((long long)bA*S_ + selB)*D_ + c0;
                float2 x0 = *reinterpret_cast<const float2*>(Xf + o0);
                float2 x1v = *reinterpret_cast<const float2*>(Xf + o1);
                *reinterpret_cast<float2*>(Cb + o0) =
                    make_float2(x0.x + wA*(a0.x + acc[ii][j8][0]), x0.y + wA*(a0.y + acc[ii][j8][1]));
                *reinterpret_cast<float2*>(Cb + o1) =
                    make_float2(x1v.x + wB*(a1.x + acc[ii][j8][2]), x1v.y + wB*(a1.y + acc[ii][j8][3]));
            }
        }
    }
}

// ---------------- fused flash attention: double-buffered, 2 CTAs/SM ----------------
#define FA_STAGE 32768
#define FA_SMEM (32768 + 2*FA_STAGE)

__global__ void __launch_bounds__(256, 2) flash_kernel(
    const __nv_bfloat16* __restrict__ Q, const __nv_bfloat16* __restrict__ K,
    const __nv_bfloat16* __restrict__ V, __nv_bfloat16* __restrict__ Ob)
{
    extern __shared__ char smem[];
    uint32_t sq = smem_u32(smem);
    int tid = threadIdx.x, warp = tid >> 5, lane = tid & 31;
    int qt = blockIdx.x;
    int bh = blockIdx.y;
    int h = bh & (H_-1), b = bh >> 4;
    const __nv_bfloat16* Qb = Q + ((long long)bh*T_ + qt*128)*HD_;
    const __nv_bfloat16* Kb = K + (long long)bh*T_*HD_;
    const __nv_bfloat16* Vb = V + (long long)bh*T_*HD_;

    #pragma unroll
    for (int i = 0; i < 8; i++){
        int ch = tid + i*256;
        int r = ch >> 4, c = ch & 15;
        cpasync16(sq + r*256 + (c >> 3)*128 + (((c & 7) ^ (r & 7)) << 4),
                  (const char*)(Qb + (long long)r*HD_) + c*16);
    }
    auto load_kv = [&](int s){
        uint32_t base = sq + 32768 + (s & 1)*FA_STAGE;
        const __nv_bfloat16* Kt = Kb + (long long)s*64*HD_;
        const __nv_bfloat16* Vt = Vb + (long long)s*64*HD_;
        #pragma unroll
        for (int i = 0; i < 4; i++){
            int ch = tid + i*256;
            int r = ch >> 4, c = ch & 15;
            uint32_t off = r*256 + (c >> 3)*128 + (((c & 7) ^ (r & 7)) << 4);
            cpasync16(base + off,         (const char*)(Kt + (long long)r*HD_) + c*16);
            cpasync16(base + 16384 + off, (const char*)(Vt + (long long)r*HD_) + c*16);
        }
        asm volatile("cp.async.commit_group;" ::: "memory");
    };
    load_kv(0);
    load_kv(1);

    const int qr0 = warp*16;
    float o[16][4];
    #pragma unroll
    for (int j=0;j<16;j++)
        #pragma unroll
        for (int e=0;e<4;e++) o[j][e] = 0.f;
    float m0 = -1e30f, m1 = -1e30f, l0 = 0.f, l1 = 0.f;
    const float sc = 0.08838834764831845f;

    int a_row  = qr0 + ((lane >> 3) & 1)*8 + (lane & 7);
    int a_kq   = (lane >> 4) * 8;
    int b_row  = (lane >> 4)*8 + (lane & 7);
    int b_kq   = ((lane >> 3) & 1) * 8;
    int v_krow = ((lane >> 3) & 1)*8 + (lane & 7);
    int v_ncol = (lane >> 4) * 8;

    for (int s = 0; s < 16; s++){
        if (s + 1 < 16) asm volatile("cp.async.wait_group 1;" ::: "memory");
        else            asm volatile("cp.async.wait_group 0;" ::: "memory");
        __syncthreads();

        uint32_t Kbase = sq + 32768 + (s & 1)*FA_STAGE;
        uint32_t Vbase = Kbase + 16384;

        float sv[8][4];
        #pragma unroll
        for (int j=0;j<8;j++)
            #pragma unroll
            for (int e=0;e<4;e++) sv[j][e] = 0.f;

        #pragma unroll
        for (int kk = 0; kk < 8; kk++){
            uint32_t af[4];
            int cA = (kk*16 + a_kq) >> 3;
            ldsm_x4(af, sq + a_row*256 + (cA >> 3)*128 + (((cA & 7) ^ (a_row & 7)) << 4));
            #pragma unroll
            for (int jj = 0; jj < 4; jj++){
                uint32_t bfm[4];
                int nrow = jj*16 + b_row;
                int cB = (kk*16 + b_kq) >> 3;
                ldsm_x4(bfm, Kbase + nrow*256 + (cB >> 3)*128 + (((cB & 7) ^ (nrow & 7)) << 4));
                mma16816(sv[2*jj],   af, bfm[0], bfm[1]);
                mma16816(sv[2*jj+1], af, bfm[2], bfm[3]);
            }
        }

        float rm0 = -1e30f, rm1 = -1e30f;
        #pragma unroll
        for (int j=0;j<8;j++){
            sv[j][0] *= sc; sv[j][1] *= sc; sv[j][2] *= sc; sv[j][3] *= sc;
            rm0 = fmaxf(rm0, fmaxf(sv[j][0], sv[j][1]));
            rm1 = fmaxf(rm1, fmaxf(sv[j][2], sv[j][3]));
        }
        rm0 = fmaxf(rm0, __shfl_xor_sync(0xffffffffu, rm0, 1));
        rm0 = fmaxf(rm0, __shfl_xor_sync(0xffffffffu, rm0, 2));
        rm1 = fmaxf(rm1, __shfl_xor_sync(0xffffffffu, rm1, 1));
        rm1 = fmaxf(rm1, __shfl_xor_sync(0xffffffffu, rm1, 2));
        float mn0 = fmaxf(m0, rm0), mn1 = fmaxf(m1, rm1);
        float rs0 = 0.f, rs1 = 0.f;
        #pragma unroll
        for (int j=0;j<8;j++){
            sv[j][0] = __expf(sv[j][0] - mn0);
            sv[j][1] = __expf(sv[j][1] - mn0);
            sv[j][2] = __expf(sv[j][2] - mn1);
            sv[j][3] = __expf(sv[j][3] - mn1);
            rs0 += sv[j][0] + sv[j][1];
            rs1 += sv[j][2] + sv[j][3];
        }
        rs0 += __shfl_xor_sync(0xffffffffu, rs0, 1);
        rs0 += __shfl_xor_sync(0xffffffffu, rs0, 2);
        rs1 += __shfl_xor_sync(0xffffffffu, rs1, 1);
        rs1 += __shfl_xor_sync(0xffffffffu, rs1, 2);
        float c0 = __expf(m0 - mn0), c1 = __expf(m1 - mn1);
        l0 = l0*c0 + rs0;  l1 = l1*c1 + rs1;
        m0 = mn0;  m1 = mn1;
        #pragma unroll
        for (int j=0;j<16;j++){
            o[j][0] *= c0; o[j][1] *= c0; o[j][2] *= c1; o[j][3] *= c1;
        }

        #pragma unroll
        for (int k2 = 0; k2 < 4; k2++){
            uint32_t pa[4];
            pa[0] = pack_bf16x2(sv[2*k2][0],   sv[2*k2][1]);
            pa[1] = pack_bf16x2(sv[2*k2][2],   sv[2*k2][3]);
            pa[2] = pack_bf16x2(sv[2*k2+1][0], sv[2*k2+1][1]);
            pa[3] = pack_bf16x2(sv[2*k2+1][2], sv[2*k2+1][3]);
            int krow = k2*16 + v_krow;
            #pragma unroll
            for (int jj = 0; jj < 8; jj++){
                uint32_t bv[4];
                int ncol = jj*16 + v_ncol;
                ldsm_x4_t(bv, Vbase + krow*256 + ((ncol >> 6) & 1)*128
                              + ((((ncol >> 3) & 7) ^ (krow & 7)) << 4));
                mma16816(o[2*jj],   pa, bv[0], bv[1]);
                mma16816(o[2*jj+1], pa, bv[2], bv[3]);
            }
        }
        __syncthreads();
        if (s + 2 < 16) load_kv(s + 2);
    }

    float il0 = __frcp_rn(l0), il1 = __frcp_rn(l1);
    int t0 = qt*128 + qr0 + (lane >> 2);
    long long base0 = ((long long)b*T_ + t0)*D_ + h*HD_;
    long long base1 = base0 + 8LL*D_;
    #pragma unroll
    for (int j=0;j<16;j++){
        int col = j*8 + (lane & 3)*2;
        *reinterpret_cast<uint32_t*>(Ob + base0 + col) = pack_bf16x2(o[j][0]*il0, o[j][1]*il0);
        *reinterpret_cast<uint32_t*>(Ob + base1 + col) = pack_bf16x2(o[j][2]*il1, o[j][3]*il1);
    }
}

// ---------------- elementwise / reduction kernels ----------------

__global__ void cvt_qkv_kernel(const float* __restrict__ wq, const float* __restrict__ wk,
                               const float* __restrict__ wv){
    const int SEG = 1 << 20;
    for (int i = blockIdx.x*blockDim.x + threadIdx.x; i < 3*SEG; i += gridDim.x*blockDim.x){
        int seg = i >> 20;
        long long off = i & (SEG-1);
        const float* src = (seg == 0) ? wq : (seg == 1) ? wk : wv;
        __nv_bfloat16* dst = g_wqkv + (long long)seg*D_*D_;
        float4 v = reinterpret_cast<const float4*>(src)[off];
        __nv_bfloat162* o = reinterpret_cast<__nv_bfloat162*>(dst) + off*2;
        o[0] = __floats2bfloat162_rn(v.x, v.y);
        o[1] = __floats2bfloat162_rn(v.z, v.w);
    }
}

__global__ void cvt_rest_kernel(const float* __restrict__ wo, const float* __restrict__ w1,
                                const float* __restrict__ w3, const float* __restrict__ w2){
    const int SEG = 1 << 20;
    for (long long i = blockIdx.x*(long long)blockDim.x + threadIdx.x;
         i < 13LL*SEG; i += (long long)gridDim.x*blockDim.x){
        int seg = (int)(i >> 20);
        const float* src; __nv_bfloat16* dst; long long off;
        if (seg < 1){        off = i;            src = wo; dst = g_wo_b; }
        else if (seg < 5){   off = i - 1LL*SEG;  src = w1; dst = g_w1_b; }
        else if (seg < 9){   off = i - 5LL*SEG;  src = w3; dst = g_w3_b; }
        else{                off = i - 9LL*SEG;  src = w2; dst = g_w2_b; }
        float4 v = reinterpret_cast<const float4*>(src)[off];
        __nv_bfloat162* o = reinterpret_cast<__nv_bfloat162*>(dst) + off*2;
        o[0] = __floats2bfloat162_rn(v.x, v.y);
        o[1] = __floats2bfloat162_rn(v.z, v.w);
    }
}

__global__ void __launch_bounds__(256) router_kernel(const float* __restrict__ x,
                                                     const float* __restrict__ wr){
    int row = blockIdx.x*8 + (threadIdx.x >> 5);
    int lane = threadIdx.x & 31;
    const float* xr = x + (long long)row * D_;
    float s = 0.f;
    #pragma unroll 8
    for (int i = lane; i < D_; i += 32) s += xr[i] * wr[i];
    #pragma unroll
    for (int o=16;o;o>>=1) s += __shfl_xor_sync(0xffffffffu, s, o);
    if (!lane) g_logits[row] = s;
}

// chunked exact rank counting: grid (16, 4, B), partial ranks, no atomics
__global__ void __launch_bounds__(256) rank_kernel(){
    __shared__ float sv[1024];
    int b = blockIdx.z, c = blockIdx.y;
    int i = blockIdx.x*256 + threadIdx.x;
    for (int j = threadIdx.x; j < 1024; j += 256) sv[j] = g_logits[b*S_ + c*1024 + j];
    __syncthreads();
    float v = g_logits[b*S_ + i];
    int base = c*1024;
    int rank = 0;
    #pragma unroll 8
    for (int j = 0; j < 1024; j++){
        float vj = sv[j];
        rank += (vj > v) || (vj == v && (base + j) < i);
    }
    g_rankp[((long long)c*B_ + b)*S_ + i] = rank;
}

// compaction + router softmax
__global__ void __launch_bounds__(1024) compact_kernel(){
    __shared__ int   scn[1024];
    __shared__ float selv[T_];
    __shared__ float red[1024];
    int b = blockIdx.x, tid = threadIdx.x;
    int base_i = tid*4;
    float v[4]; int rank[4];
    #pragma unroll
    for (int e=0;e<4;e++){
        int i = base_i + e;
        v[e] = g_logits[b*S_ + i];
        int r = 0;
        #pragma unroll
        for (int c=0;c<4;c++) r += g_rankp[((long long)c*B_ + b)*S_ + i];
        rank[e] = r;
    }
    int flag[4]; int cnt = 0;
    #pragma unroll
    for (int e=0;e<4;e++){ flag[e] = rank[e] < T_; cnt += flag[e]; }
    scn[tid] = cnt; __syncthreads();
    for (int off=1; off<1024; off<<=1){
        int t = 0;
        if (tid >= off) t = scn[tid-off];
        __syncthreads();
        scn[tid] += t;
        __syncthreads();
    }
    int pos = scn[tid] - cnt;
    #pragma unroll
    for (int e=0;e<4;e++){
        int i = base_i + e;
        int p = -1;
        if (flag[e]){ p = pos++; g_sel[b*T_+p] = i; selv[p] = v[e]; }
        g_pos[b*S_ + i] = p;
    }
    __syncthreads();
    float sval = selv[tid];
    red[tid] = sval; __syncthreads();
    for (int off=512; off; off>>=1){ if (tid < off) red[tid] = fmaxf(red[tid], red[tid+off]); __syncthreads(); }
    float mx = red[0]; __syncthreads();
    float ex = __expf(sval - mx);
    red[tid] = ex; __syncthreads();
    for (int off=512; off; off>>=1){ if (tid < off) red[tid] += red[tid+off]; __syncthreads(); }
    g_rw[b*T_ + tid] = ex / red[0];
}

__device__ __forceinline__ float block_sum_256(float v, float* sh){
    #pragma unroll
    for (int o=16;o;o>>=1) v += __shfl_xor_sync(0xffffffffu, v, o);
    if ((threadIdx.x & 31) == 0) sh[threadIdx.x >> 5] = v;
    __syncthreads();
    if (threadIdx.x == 0){ float t=0; for (int w=0;w<8;w++) t += sh[w]; sh[0] = t; }
    __syncthreads();
    float r = sh[0];
    __syncthreads();
    return r;
}

__global__ void __launch_bounds__(256) gather_rms_kernel(const float* __restrict__ x,
                                                         const float* __restrict__ g1){
    __shared__ float sh[8];
    int bt = blockIdx.x;
    int b = bt >> 10;
    int s = g_sel[bt];
    const float* xr = x + ((long long)b*S_ + s) * D_;
    float vals[8]; float ss = 0.f;
    #pragma unroll
    for (int e=0;e<8;e++){ float val = xr[threadIdx.x + e*256]; vals[e] = val; ss += val*val; }
    float tot = block_sum_256(ss, sh);
    float inv = rsqrtf(tot / D_ + 1e-6f);
    long long base = (long long)bt * D_;
    #pragma unroll
    for (int e=0;e<8;e++){
        int d = threadIdx.x + e*256;
        g_h[base+d] = __float2bfloat16(vals[e] * inv * g1[d]);
    }
}

__global__ void __launch_bounds__(256) resid_rms_kernel(const float* __restrict__ g2){
    __shared__ float sh[8];
    long long base = (long long)blockIdx.x * D_;
    float vals[8]; float ss = 0.f;
    #pragma unroll
    for (int e=0;e<8;e++){
        int d = threadIdx.x + e*256;
        float val = g_x1[base+d];
        vals[e] = val; ss += val*val;
    }
    float tot = block_sum_256(ss, sh);
    float inv = rsqrtf(tot / D_ + 1e-6f);
    #pragma unroll
    for (int e=0;e<8;e++){
        int d = threadIdx.x + e*256;
        g_h2[base+d] = __float2bfloat16(vals[e] * inv * g2[d]);
    }
}

__global__ void __launch_bounds__(256) final_copy_kernel(const float* __restrict__ x,
                                                         float* __restrict__ out){
    int bs = blockIdx.x;
    if (g_pos[bs] >= 0) return;
    long long rb = (long long)bs * D_;
    #pragma unroll
    for (int e=0;e<2;e++){
        int i = threadIdx.x + e*256;
        reinterpret_cast<float4*>(out + rb)[i] =
            reinterpret_cast<const float4*>(x + rb)[i];
    }
}

// ---------------- host orchestration ----------------
#define GETP(sym_) ([&]{ void* p_ = nullptr; cudaGetSymbolAddress(&p_, sym_); return p_; }())

extern "C" void kernel_launch(void* const* d_in, const int* in_sizes, int n_in,
                              void* d_out, int out_size)
{
    const float* x     = (const float*)d_in[0];
    const float* freqs = (const float*)d_in[2];
    const float* wr    = (const float*)d_in[3];
    const float* g1    = (const float*)d_in[4];
    const float* wq    = (const float*)d_in[5];
    const float* wk    = (const float*)d_in[6];
    const float* wv    = (const float*)d_in[7];
    const float* wo    = (const float*)d_in[8];
    const float* g2    = (const float*)d_in[9];
    const float* w1    = (const float*)d_in[10];
    const float* w3    = (const float*)d_in[11];
    const float* w2    = (const float*)d_in[12];
    float* out = (float*)d_out;

    static bool init_done = false;
    static cudaStream_t s2;
    static cudaEvent_t ev_fork, ev_join;
    if (!init_done){
        cudaFuncSetAttribute(gemm3<1>, cudaFuncAttributeMaxDynamicSharedMemorySize, GEMM_SMEM);
        cudaFuncSetAttribute(gemm3<2>, cudaFuncAttributeMaxDynamicSharedMemorySize, GEMM_SMEM);
        cudaFuncSetAttribute(gemm3<4>, cudaFuncAttributeMaxDynamicSharedMemorySize, GEMM_SMEM);
        cudaFuncSetAttribute(gemm3<5>, cudaFuncAttributeMaxDynamicSharedMemorySize, GEMM_SMEM);
        cudaFuncSetAttribute(gemm3<6>, cudaFuncAttributeMaxDynamicSharedMemorySize, GEMM_SMEM);
        cudaFuncSetAttribute(flash_kernel, cudaFuncAttributeMaxDynamicSharedMemorySize, FA_SMEM);
        cudaStreamCreateWithFlags(&s2, cudaStreamNonBlocking);
        cudaEventCreateWithFlags(&ev_fork, cudaEventDisableTiming);
        cudaEventCreateWithFlags(&ev_join, cudaEventDisableTiming);
        init_done = true;
    }

    __nv_bfloat16* p_wqkv = (__nv_bfloat16*)GETP(g_wqkv);
    __nv_bfloat16* p_wo = (__nv_bfloat16*)GETP(g_wo_b);
    __nv_bfloat16* p_w1 = (__nv_bfloat16*)GETP(g_w1_b);
    __nv_bfloat16* p_w3 = (__nv_bfloat16*)GETP(g_w3_b);
    __nv_bfloat16* p_w2 = (__nv_bfloat16*)GETP(g_w2_b);
    __nv_bfloat16* p_h  = (__nv_bfloat16*)GETP(g_h);
    __nv_bfloat16* p_qb = (__nv_bfloat16*)GETP(g_qb);
    __nv_bfloat16* p_kb = (__nv_bfloat16*)GETP(g_kb);
    __nv_bfloat16* p_vb = (__nv_bfloat16*)GETP(g_vb);
    __nv_bfloat16* p_ob = (__nv_bfloat16*)GETP(g_ob);
    __nv_bfloat16* p_h2 = (__nv_bfloat16*)GETP(g_h2);
    __nv_bfloat16* p_u  = (__nv_bfloat16*)GETP(g_u);
    __nv_bfloat16* p_ac = (__nv_bfloat16*)GETP(g_act);
    float* p_x1 = (float*)GETP(g_x1);

    // fork: side stream converts wo|w1|w3|w2, overlapped with main chain (R12 structure)
    cudaEventRecord(ev_fork, 0);
    cudaStreamWaitEvent(s2, ev_fork, 0);
    cvt_rest_kernel<<<4096, 256, 0, s2>>>(wo, w1, w3, w2);
    cudaEventRecord(ev_join, s2);

    // main chain
    cvt_qkv_kernel<<<2048, 256>>>(wq, wk, wv);
    router_kernel<<<B_*S_/8, 256>>>(x, wr);
    rank_kernel<<<dim3(16, 4, B_), 256>>>();
    compact_kernel<<<B_, 1024>>>();
    gather_rms_kernel<<<M_, 256>>>(x, g1);

    // QKV GEMM with fused RoPE epilogue
    gemm3<4><<<dim3(D_/BN, M_/BM, 3), 256, GEMM_SMEM>>>(p_h, p_wqkv, nullptr,
        D_, D_, D_, D_, 0, (long long)D_*D_, 0, freqs, nullptr, nullptr);

    // fused flash attention -> g_ob [b,t,d] bf16
    flash_kernel<<<dim3(T_/128, B_*H_), 256, FA_SMEM>>>(p_qb, p_kb, p_vb, p_ob);

    // join: wo/w1/w3/w2 must be converted from here on
    cudaStreamWaitEvent(0, ev_join, 0);

    // attn projection + gathered residual: x1 = x[b,sel] + ob@wo
    gemm3<6><<<dim3(D_/BN, M_/BM, 1), 256, GEMM_SMEM>>>(p_ob, p_wo, p_x1,
        D_, D_, D_, D_, 0,0,0, nullptr, nullptr, x);

    // rmsnorm2
    resid_rms_kernel<<<M_, 256>>>(g2);

    // FFN: u = h2@w1 (bf16) ; act = silu(u)*(h2@w3)
    gemm3<2><<<dim3(F_/BN, M_/BM, 1), 256, GEMM_SMEM>>>(p_h2, p_w1, nullptr,
        D_, D_, F_, F_, 0,0,0, nullptr, p_u, nullptr);
    gemm3<1><<<dim3(F_/BN, M_/BM, 1), 256, GEMM_SMEM>>>(p_h2, p_w3, nullptr,
        D_, D_, F_, F_, 0,0,0, p_u, p_ac, nullptr);

    // w2 GEMM with fused final scatter-add
    gemm3<5><<<dim3(D_/BN, M_/BM, 1), 256, GEMM_SMEM>>>(p_ac, p_w2, out,
        F_, F_, D_, D_, 0,0,0, p_x1, nullptr, x);

    // copy non-selected rows
    final_copy_kernel<<<B_*S_, 256>>>(x, out);
}

// round 15
// speedup vs baseline: 1.5167x; 1.0027x over previous
#include <cuda_runtime.h>
#include <cuda_bf16.h>
#include <cstdint>

// Problem dims
#define B_  4
#define S_  4096
#define D_  2048
#define T_  1024
#define H_  16
#define HD_ 128
#define F_  8192
#define M_  (B_*T_)

// ---------------- device scratch ----------------
#define DEVBUF(type, name, count) __device__ __align__(256) type name[count]

DEVBUF(__nv_bfloat16, g_wqkv, 3LL*D_*D_);   // packed [wq|wk|wv]
DEVBUF(__nv_bfloat16, g_wo_b, D_*D_);
DEVBUF(__nv_bfloat16, g_w1_b, D_*F_);
DEVBUF(__nv_bfloat16, g_w3_b, D_*F_);
DEVBUF(__nv_bfloat16, g_w2_b, F_*D_);

DEVBUF(float, g_logits, B_*S_);
DEVBUF(int,   g_rankp,  8LL*B_*S_);
DEVBUF(int,   g_sel,    B_*T_);
DEVBUF(int,   g_pos,    B_*S_);
DEVBUF(float, g_rw,     B_*T_);

DEVBUF(__nv_bfloat16, g_h,   M_*D_);
DEVBUF(__nv_bfloat16, g_qb,  M_*D_);        // [b,h,t,hd] (rope'd)
DEVBUF(__nv_bfloat16, g_kb,  M_*D_);
DEVBUF(__nv_bfloat16, g_vb,  M_*D_);
DEVBUF(__nv_bfloat16, g_ob,  M_*D_);        // attn out [b,t,d] bf16
DEVBUF(float,         g_x1,  M_*D_);        // x_gathered + attn proj
DEVBUF(__nv_bfloat16, g_h2,  M_*D_);
DEVBUF(__nv_bfloat16, g_u,   M_*F_);        // bf16 u
DEVBUF(__nv_bfloat16, g_act, M_*F_);

// ---------------- PTX helpers ----------------
__device__ __forceinline__ uint32_t smem_u32(const void* p){
    uint32_t a;
    asm("{ .reg .u64 t; cvta.to.shared.u64 t, %1; cvt.u32.u64 %0, t; }" : "=r"(a) : "l"(p));
    return a;
}
__device__ __forceinline__ void cpasync16(uint32_t dst, const void* src){
    asm volatile("cp.async.cg.shared.global [%0], [%1], 16;" :: "r"(dst), "l"(src));
}
__device__ __forceinline__ void ldsm_x4(uint32_t* r, uint32_t addr){
    asm volatile("ldmatrix.sync.aligned.m8n8.x4.shared.b16 {%0,%1,%2,%3}, [%4];"
        : "=r"(r[0]), "=r"(r[1]), "=r"(r[2]), "=r"(r[3]) : "r"(addr));
}
__device__ __forceinline__ void ldsm_x4_t(uint32_t* r, uint32_t addr){
    asm volatile("ldmatrix.sync.aligned.m8n8.x4.trans.shared.b16 {%0,%1,%2,%3}, [%4];"
        : "=r"(r[0]), "=r"(r[1]), "=r"(r[2]), "=r"(r[3]) : "r"(addr));
}
__device__ __forceinline__ void mma16816(float* c, const uint32_t* a, uint32_t b0, uint32_t b1){
    asm volatile("mma.sync.aligned.m16n8k16.row.col.f32.bf16.bf16.f32 "
        "{%0,%1,%2,%3}, {%4,%5,%6,%7}, {%8,%9}, {%0,%1,%2,%3};"
        : "+f"(c[0]), "+f"(c[1]), "+f"(c[2]), "+f"(c[3])
        : "r"(a[0]), "r"(a[1]), "r"(a[2]), "r"(a[3]), "r"(b0), "r"(b1));
}
__device__ __forceinline__ uint32_t pack_bf16x2(float lo, float hi){
    __nv_bfloat162 v = __floats2bfloat162_rn(lo, hi);
    return *reinterpret_cast<uint32_t*>(&v);
}

// ---------------- raw mma.sync GEMM (128x128 CTA, 2 CTAs/SM) ----------------
// EPI=1: silu(Ubf)*acc -> bf16; EPI=2: bf16 store
// EPI=4: QKV+RoPE epilogue (z=0 q rope, z=1 k rope, z=2 v plain), Uv=freqs
// EPI=5: fused final: out[b,sel] = x + rw*(x1 + acc); Uv=x1, Xf=x, C=out
// EPI=6: x1 = x_gathered + acc; Xf=x, C=x1

#define BM 128
#define BN 128
#define BK 64
#define STAGE_B 32768
#define GEMM_SMEM (3*STAGE_B)

__device__ __forceinline__ void ldA_128x64(const __nv_bfloat16* g, int ld, uint32_t sbase, int tid){
    #pragma unroll
    for (int i = 0; i < 4; i++){
        int ch = tid + i*256;
        int r = ch >> 3, c = ch & 7;
        cpasync16(sbase + r*128 + (((c ^ (r & 7))) << 4),
                  (const char*)(g + (long long)r*ld) + c*16);
    }
}
__device__ __forceinline__ void ldB_64x128(const __nv_bfloat16* g, int ld, uint32_t sbase, int tid){
    #pragma unroll
    for (int i = 0; i < 4; i++){
        int ch = tid + i*256;
        int r = ch >> 4, c = ch & 15;
        int half = c >> 3, c8 = c & 7;
        cpasync16(sbase + r*256 + half*128 + ((c8 ^ (r & 7)) << 4),
                  (const char*)(g + (long long)r*ld) + c*16);
    }
}

template<int EPI>
__global__ void __launch_bounds__(256, 2) gemm3(
    const __nv_bfloat16* __restrict__ A, const __nv_bfloat16* __restrict__ Bm,
    float* __restrict__ C, int K, int lda, int ldb, int ldc,
    long long sA, long long sB, long long sC,
    const void* __restrict__ Uv, __nv_bfloat16* __restrict__ Obf,
    const float* __restrict__ Xf)
{
    extern __shared__ char smem[];
    uint32_t sb = smem_u32(smem);
    int tid = threadIdx.x, warp = tid >> 5, lane = tid & 31;
    int z = blockIdx.z;
    const __nv_bfloat16* Ab = A + (long long)z*sA + (long long)blockIdx.y*BM*lda;
    const __nv_bfloat16* Bb = Bm + (long long)z*sB;
    float* Cb = C ? C + (long long)z*sC : nullptr;
    __nv_bfloat16* Ob = Obf ? Obf + (long long)z*sC : nullptr;
    const int bn = blockIdx.x*BN;

    int wm = (warp & 3) * 32;
    int wn = (warp >> 2) * 64;

    float acc[2][8][4];
    #pragma unroll
    for (int i=0;i<2;i++)
        #pragma unroll
        for (int j=0;j<8;j++)
            #pragma unroll
            for (int e=0;e<4;e++) acc[i][j][e] = 0.f;

    const int NS = K >> 6;

    auto load_stage = [&](int s){
        uint32_t base = sb + (s % 3)*STAGE_B;
        int k0 = s*BK;
        ldA_128x64(Ab + k0, lda, base, tid);
        ldB_64x128(Bb + (long long)k0*ldb + bn, ldb, base + 16384, tid);
        asm volatile("cp.async.commit_group;" ::: "memory");
    };

    load_stage(0);
    if (NS > 1) load_stage(1);

    int a_row_lo = wm + ((lane >> 3) & 1)*8 + (lane & 7);
    int a_kq     = (lane >> 4) * 8;
    int b0_krow  = ((lane >> 3) & 1)*8 + (lane & 7);
    int b0_ncol  = wn + (lane >> 4)*8;

    for (int s = 0; s < NS; s++){
        if (s + 1 < NS) asm volatile("cp.async.wait_group 1;" ::: "memory");
        else            asm volatile("cp.async.wait_group 0;" ::: "memory");
        __syncthreads();

        if (s + 2 < NS) load_stage(s + 2);

        uint32_t Abase = sb + (s % 3)*STAGE_B;
        uint32_t Bbase = Abase + 16384;

        #pragma unroll
        for (int kk = 0; kk < BK; kk += 16){
            uint32_t af[2][4];
            #pragma unroll
            for (int ii = 0; ii < 2; ii++){
                int mrow = a_row_lo + ii*16;
                int kb = kk + a_kq;
                ldsm_x4(af[ii], Abase + mrow*128 + ((((kb >> 3) ^ (mrow & 7))) << 4));
            }
            uint32_t bfm[4][4];
            #pragma unroll
            for (int jj = 0; jj < 4; jj++){
                int krow = kk + b0_krow;
                int ncol = b0_ncol + jj*16;
                ldsm_x4_t(bfm[jj], Bbase + krow*256 + ((ncol >> 6) & 1)*128
                                 + ((((ncol >> 3) & 7) ^ (krow & 7)) << 4));
            }
            #pragma unroll
            for (int ii = 0; ii < 2; ii++)
                #pragma unroll
                for (int jj = 0; jj < 4; jj++){
                    mma16816(acc[ii][2*jj],   af[ii], bfm[jj][0], bfm[jj][1]);
                    mma16816(acc[ii][2*jj+1], af[ii], bfm[jj][2], bfm[jj][3]);
                }
        }
        __syncthreads();
    }

    if (EPI == 4){
        int h = blockIdx.x;
        if (z == 2){
            #pragma unroll
            for (int ii = 0; ii < 2; ii++){
                int r0 = blockIdx.y*BM + wm + ii*16 + (lane >> 2);
                int b = r0 >> 10, t = r0 & (T_-1);
                long long dbase = ((long long)(b*H_ + h)*T_ + t)*HD_;
                #pragma unroll
                for (int j8 = 0; j8 < 8; j8++){
                    int wc = wn + j8*8 + (lane & 3)*2;
                    *reinterpret_cast<uint32_t*>(g_vb + dbase + wc) =
                        pack_bf16x2(acc[ii][j8][0], acc[ii][j8][1]);
                    *reinterpret_cast<uint32_t*>(g_vb + dbase + 8LL*HD_ + wc) =
                        pack_bf16x2(acc[ii][j8][2], acc[ii][j8][3]);
                }
            }
        } else {
            float* sf = reinterpret_cast<float*>(smem);
            #pragma unroll
            for (int ii = 0; ii < 2; ii++){
                int sr = wm + ii*16 + (lane >> 2);
                #pragma unroll
                for (int j8 = 0; j8 < 8; j8++){
                    int sc = wn + j8*8 + (lane & 3)*2;
                    sf[sr*136 + sc]     = acc[ii][j8][0];
                    sf[sr*136 + sc + 1] = acc[ii][j8][1];
                    sf[(sr+8)*136 + sc]     = acc[ii][j8][2];
                    sf[(sr+8)*136 + sc + 1] = acc[ii][j8][3];
                }
            }
            __syncthreads();
            const float* fr = (const float*)Uv;
            __nv_bfloat16* dstp = (z == 0) ? g_qb : g_kb;
            #pragma unroll
            for (int i = 0; i < 32; i++){
                int idx = tid + i*256;
                int row = idx >> 6;
                int d2  = (idx & 63) * 2;
                int r = blockIdx.y*BM + row;
                int b = r >> 10, t = r & (T_-1);
                float v0 = sf[row*136 + d2];
                float v1 = sf[row*136 + d2 + 1];
                float p0 = sf[row*136 + (d2 ^ 64)];
                float p1 = sf[row*136 + (d2 ^ 64) + 1];
                int j0 = d2 & 63;
                float c0 = fr[(t*64 + j0)*2],     s0 = fr[(t*64 + j0)*2 + 1];
                float c1 = fr[(t*64 + j0 + 1)*2], s1 = fr[(t*64 + j0 + 1)*2 + 1];
                float o0, o1;
                if (d2 < 64){ o0 = v0*c0 - p0*s0; o1 = v1*c1 - p1*s1; }
                else        { o0 = p0*s0 + v0*c0; o1 = p1*s1 + v1*c1; }
                long long dst = ((long long)(b*H_ + h)*T_ + t)*HD_ + d2;
                *reinterpret_cast<uint32_t*>(dstp + dst) = pack_bf16x2(o0, o1);
            }
        }
        return;
    }

    #pragma unroll
    for (int ii = 0; ii < 2; ii++){
        int r0 = blockIdx.y*BM + wm + ii*16 + (lane >> 2);
        int selA = 0, selB = 0; float wA = 0.f, wB = 0.f; int bA = 0;
        if (EPI == 5 || EPI == 6){
            bA = r0 >> 10;
            selA = g_sel[r0];
            selB = g_sel[r0 + 8];
            if (EPI == 5){ wA = g_rw[r0]; wB = g_rw[r0 + 8]; }
        }
        #pragma unroll
        for (int j8 = 0; j8 < 8; j8++){
            int c0 = bn + wn + j8*8 + (lane & 3)*2;
            long long i0 = (long long)r0*ldc + c0;
            long long i1 = i0 + 8*(long long)ldc;
            if (EPI == 1){
                const __nv_bfloat16* Ub = (const __nv_bfloat16*)Uv;
                __nv_bfloat162 u0 = *reinterpret_cast<const __nv_bfloat162*>(Ub + i0);
                __nv_bfloat162 u1 = *reinterpret_cast<const __nv_bfloat162*>(Ub + i1);
                float ux = __bfloat162float(u0.x), uy = __bfloat162float(u0.y);
                float uz = __bfloat162float(u1.x), uw = __bfloat162float(u1.y);
                float s0 = __fdividef(ux, 1.f + __expf(-ux)) * acc[ii][j8][0];
                float s1 = __fdividef(uy, 1.f + __expf(-uy)) * acc[ii][j8][1];
                float s2 = __fdividef(uz, 1.f + __expf(-uz)) * acc[ii][j8][2];
                float s3 = __fdividef(uw, 1.f + __expf(-uw)) * acc[ii][j8][3];
                *reinterpret_cast<uint32_t*>(Ob + i0) = pack_bf16x2(s0, s1);
                *reinterpret_cast<uint32_t*>(Ob + i1) = pack_bf16x2(s2, s3);
            } else if (EPI == 2){
                *reinterpret_cast<uint32_t*>(Ob + i0) = pack_bf16x2(acc[ii][j8][0], acc[ii][j8][1]);
                *reinterpret_cast<uint32_t*>(Ob + i1) = pack_bf16x2(acc[ii][j8][2], acc[ii][j8][3]);
            } else if (EPI == 6){
                long long o0 = ((long long)bA*S_ + selA)*D_ + c0;
                long long o1 = ((long long)bA*S_ + selB)*D_ + c0;
                float2 x0 = *reinterpret_cast<const float2*>(Xf + o0);
                float2 x1v = *reinterpret_cast<const float2*>(Xf + o1);
                *reinterpret_cast<float2*>(Cb + i0) = make_float2(acc[ii][j8][0] + x0.x, acc[ii][j8][1] + x0.y);
                *reinterpret_cast<float2*>(Cb + i1) = make_float2(acc[ii][j8][2] + x1v.x, acc[ii][j8][3] + x1v.y);
            } else { // EPI == 5
                const float* X1 = (const float*)Uv;
                float2 a0 = *reinterpret_cast<const float2*>(X1 + i0);
                float2 a1 = *reinterpret_cast<const float2*>(X1 + i1);
                long long o0 = ((long long)bA*S_ + selA)*D_ + c0;
                long long o1 = ((long long)bA*S_ + selB)*D_ + c0;
                float2 x0 = *reinterpret_cast<const float2*>(Xf + o0);
                float2 x1v = *reinterpret_cast<const float2*>(Xf + o1);
                *reinterpret_cast<float2*>(Cb + o0) =
                    make_float2(x0.x + wA*(a0.x + acc[ii][j8][0]), x0.y + wA*(a0.y + acc[ii][j8][1]));
                *reinterpret_cast<float2*>(Cb + o1) =
                    make_float2(x1v.x + wB*(a1.x + acc[ii][j8][2]), x1v.y + wB*(a1.y + acc[ii][j8][3]));
            }
        }
    }
}

// ---------------- fused flash attention: double-buffered, 2 CTAs/SM ----------------
#define FA_STAGE 32768
#define FA_SMEM (32768 + 2*FA_STAGE)

__global__ void __launch_bounds__(256, 2) flash_kernel(
    const __nv_bfloat16* __restrict__ Q, const __nv_bfloat16* __restrict__ K,
    const __nv_bfloat16* __restrict__ V, __nv_bfloat16* __restrict__ Ob)
{
    extern __shared__ char smem[];
    uint32_t sq = smem_u32(smem);
    int tid = threadIdx.x, warp = tid >> 5, lane = tid & 31;
    int qt = blockIdx.x;
    int bh = blockIdx.y;
    int h = bh & (H_-1), b = bh >> 4;
    const __nv_bfloat16* Qb = Q + ((long long)bh*T_ + qt*128)*HD_;
    const __nv_bfloat16* Kb = K + (long long)bh*T_*HD_;
    const __nv_bfloat16* Vb = V + (long long)bh*T_*HD_;

    #pragma unroll
    for (int i = 0; i < 8; i++){
        int ch = tid + i*256;
        int r = ch >> 4, c = ch & 15;
        cpasync16(sq + r*256 + (c >> 3)*128 + (((c & 7) ^ (r & 7)) << 4),
                  (const char*)(Qb + (long long)r*HD_) + c*16);
    }
    auto load_kv = [&](int s){
        uint32_t base = sq + 32768 + (s & 1)*FA_STAGE;
        const __nv_bfloat16* Kt = Kb + (long long)s*64*HD_;
        const __nv_bfloat16* Vt = Vb + (long long)s*64*HD_;
        #pragma unroll
        for (int i = 0; i < 4; i++){
            int ch = tid + i*256;
            int r = ch >> 4, c = ch & 15;
            uint32_t off = r*256 + (c >> 3)*128 + (((c & 7) ^ (r & 7)) << 4);
            cpasync16(base + off,         (const char*)(Kt + (long long)r*HD_) + c*16);
            cpasync16(base + 16384 + off, (const char*)(Vt + (long long)r*HD_) + c*16);
        }
        asm volatile("cp.async.commit_group;" ::: "memory");
    };
    load_kv(0);
    load_kv(1);

    const int qr0 = warp*16;
    float o[16][4];
    #pragma unroll
    for (int j=0;j<16;j++)
        #pragma unroll
        for (int e=0;e<4;e++) o[j][e] = 0.f;
    float m0 = -1e30f, m1 = -1e30f, l0 = 0.f, l1 = 0.f;
    const float sc = 0.08838834764831845f;

    int a_row  = qr0 + ((lane >> 3) & 1)*8 + (lane & 7);
    int a_kq   = (lane >> 4) * 8;
    int b_row  = (lane >> 4)*8 + (lane & 7);
    int b_kq   = ((lane >> 3) & 1) * 8;
    int v_krow = ((lane >> 3) & 1)*8 + (lane & 7);
    int v_ncol = (lane >> 4) * 8;

    for (int s = 0; s < 16; s++){
        if (s + 1 < 16) asm volatile("cp.async.wait_group 1;" ::: "memory");
        else            asm volatile("cp.async.wait_group 0;" ::: "memory");
        __syncthreads();

        uint32_t Kbase = sq + 32768 + (s & 1)*FA_STAGE;
        uint32_t Vbase = Kbase + 16384;

        float sv[8][4];
        #pragma unroll
        for (int j=0;j<8;j++)
            #pragma unroll
            for (int e=0;e<4;e++) sv[j][e] = 0.f;

        #pragma unroll
        for (int kk = 0; kk < 8; kk++){
            uint32_t af[4];
            int cA = (kk*16 + a_kq) >> 3;
            ldsm_x4(af, sq + a_row*256 + (cA >> 3)*128 + (((cA & 7) ^ (a_row & 7)) << 4));
            #pragma unroll
            for (int jj = 0; jj < 4; jj++){
                uint32_t bfm[4];
                int nrow = jj*16 + b_row;
                int cB = (kk*16 + b_kq) >> 3;
                ldsm_x4(bfm, Kbase + nrow*256 + (cB >> 3)*128 + (((cB & 7) ^ (nrow & 7)) << 4));
                mma16816(sv[2*jj],   af, bfm[0], bfm[1]);
                mma16816(sv[2*jj+1], af, bfm[2], bfm[3]);
            }
        }

        float rm0 = -1e30f, rm1 = -1e30f;
        #pragma unroll
        for (int j=0;j<8;j++){
            sv[j][0] *= sc; sv[j][1] *= sc; sv[j][2] *= sc; sv[j][3] *= sc;
            rm0 = fmaxf(rm0, fmaxf(sv[j][0], sv[j][1]));
            rm1 = fmaxf(rm1, fmaxf(sv[j][2], sv[j][3]));
        }
        rm0 = fmaxf(rm0, __shfl_xor_sync(0xffffffffu, rm0, 1));
        rm0 = fmaxf(rm0, __shfl_xor_sync(0xffffffffu, rm0, 2));
        rm1 = fmaxf(rm1, __shfl_xor_sync(0xffffffffu, rm1, 1));
        rm1 = fmaxf(rm1, __shfl_xor_sync(0xffffffffu, rm1, 2));
        float mn0 = fmaxf(m0, rm0), mn1 = fmaxf(m1, rm1);
        float rs0 = 0.f, rs1 = 0.f;
        #pragma unroll
        for (int j=0;j<8;j++){
            sv[j][0] = __expf(sv[j][0] - mn0);
            sv[j][1] = __expf(sv[j][1] - mn0);
            sv[j][2] = __expf(sv[j][2] - mn1);
            sv[j][3] = __expf(sv[j][3] - mn1);
            rs0 += sv[j][0] + sv[j][1];
            rs1 += sv[j][2] + sv[j][3];
        }
        rs0 += __shfl_xor_sync(0xffffffffu, rs0, 1);
        rs0 += __shfl_xor_sync(0xffffffffu, rs0, 2);
        rs1 += __shfl_xor_sync(0xffffffffu, rs1, 1);
        rs1 += __shfl_xor_sync(0xffffffffu, rs1, 2);
        float c0 = __expf(m0 - mn0), c1 = __expf(m1 - mn1);
        l0 = l0*c0 + rs0;  l1 = l1*c1 + rs1;
        m0 = mn0;  m1 = mn1;
        #pragma unroll
        for (int j=0;j<16;j++){
            o[j][0] *= c0; o[j][1] *= c0; o[j][2] *= c1; o[j][3] *= c1;
        }

        #pragma unroll
        for (int k2 = 0; k2 < 4; k2++){
            uint32_t pa[4];
            pa[0] = pack_bf16x2(sv[2*k2][0],   sv[2*k2][1]);
            pa[1] = pack_bf16x2(sv[2*k2][2],   sv[2*k2][3]);
            pa[2] = pack_bf16x2(sv[2*k2+1][0], sv[2*k2+1][1]);
            pa[3] = pack_bf16x2(sv[2*k2+1][2], sv[2*k2+1][3]);
            int krow = k2*16 + v_krow;
            #pragma unroll
            for (int jj = 0; jj < 8; jj++){
                uint32_t bv[4];
                int ncol = jj*16 + v_ncol;
                ldsm_x4_t(bv, Vbase + krow*256 + ((ncol >> 6) & 1)*128
                              + ((((ncol >> 3) & 7) ^ (krow & 7)) << 4));
                mma16816(o[2*jj],   pa, bv[0], bv[1]);
                mma16816(o[2*jj+1], pa, bv[2], bv[3]);
            }
        }
        __syncthreads();
        if (s + 2 < 16) load_kv(s + 2);
    }

    float il0 = __frcp_rn(l0), il1 = __frcp_rn(l1);
    int t0 = qt*128 + qr0 + (lane >> 2);
    long long base0 = ((long long)b*T_ + t0)*D_ + h*HD_;
    long long base1 = base0 + 8LL*D_;
    #pragma unroll
    for (int j=0;j<16;j++){
        int col = j*8 + (lane & 3)*2;
        *reinterpret_cast<uint32_t*>(Ob + base0 + col) = pack_bf16x2(o[j][0]*il0, o[j][1]*il0);
        *reinterpret_cast<uint32_t*>(Ob + base1 + col) = pack_bf16x2(o[j][2]*il1, o[j][3]*il1);
    }
}

// ---------------- elementwise / reduction kernels ----------------

__global__ void cvt_qkv_kernel(const float* __restrict__ wq, const float* __restrict__ wk,
                               const float* __restrict__ wv){
    const int SEG = 1 << 20;
    for (int i = blockIdx.x*blockDim.x + threadIdx.x; i < 3*SEG; i += gridDim.x*blockDim.x){
        int seg = i >> 20;
        long long off = i & (SEG-1);
        const float* src = (seg == 0) ? wq : (seg == 1) ? wk : wv;
        __nv_bfloat16* dst = g_wqkv + (long long)seg*D_*D_;
        float4 v = reinterpret_cast<const float4*>(src)[off];
        __nv_bfloat162* o = reinterpret_cast<__nv_bfloat162*>(dst) + off*2;
        o[0] = __floats2bfloat162_rn(v.x, v.y);
        o[1] = __floats2bfloat162_rn(v.z, v.w);
    }
}

__global__ void cvt_rest_kernel(const float* __restrict__ wo, const float* __restrict__ w1,
                                const float* __restrict__ w3, const float* __restrict__ w2){
    const int SEG = 1 << 20;
    for (long long i = blockIdx.x*(long long)blockDim.x + threadIdx.x;
         i < 13LL*SEG; i += (long long)gridDim.x*blockDim.x){
        int seg = (int)(i >> 20);
        const float* src; __nv_bfloat16* dst; long long off;
        if (seg < 1){        off = i;            src = wo; dst = g_wo_b; }
        else if (seg < 5){   off = i - 1LL*SEG;  src = w1; dst = g_w1_b; }
        else if (seg < 9){   off = i - 5LL*SEG;  src = w3; dst = g_w3_b; }
        else{                off = i - 9LL*SEG;  src = w2; dst = g_w2_b; }
        float4 v = reinterpret_cast<const float4*>(src)[off];
        __nv_bfloat162* o = reinterpret_cast<__nv_bfloat162*>(dst) + off*2;
        o[0] = __floats2bfloat162_rn(v.x, v.y);
        o[1] = __floats2bfloat162_rn(v.z, v.w);
    }
}

__global__ void __launch_bounds__(256) router_kernel(const float* __restrict__ x,
                                                     const float* __restrict__ wr){
    int row = blockIdx.x*8 + (threadIdx.x >> 5);
    int lane = threadIdx.x & 31;
    const float* xr = x + (long long)row * D_;
    float s = 0.f;
    #pragma unroll 8
    for (int i = lane; i < D_; i += 32) s += xr[i] * wr[i];
    #pragma unroll
    for (int o=16;o;o>>=1) s += __shfl_xor_sync(0xffffffffu, s, o);
    if (!lane) g_logits[row] = s;
}

// chunked exact rank counting: grid (16, 8, B), 512-element chunks
__global__ void __launch_bounds__(256) rank_kernel(){
    __shared__ float sv[512];
    int b = blockIdx.z, c = blockIdx.y;
    int i = blockIdx.x*256 + threadIdx.x;
    for (int j = threadIdx.x; j < 512; j += 256) sv[j] = g_logits[b*S_ + c*512 + j];
    __syncthreads();
    float v = g_logits[b*S_ + i];
    int base = c*512;
    int rank = 0;
    #pragma unroll 8
    for (int j = 0; j < 512; j++){
        float vj = sv[j];
        rank += (vj > v) || (vj == v && (base + j) < i);
    }
    g_rankp[((long long)c*B_ + b)*S_ + i] = rank;
}

// compaction + router softmax
__global__ void __launch_bounds__(1024) compact_kernel(){
    __shared__ int   scn[1024];
    __shared__ float selv[T_];
    __shared__ float red[1024];
    int b = blockIdx.x, tid = threadIdx.x;
    int base_i = tid*4;
    float v[4]; int rank[4];
    #pragma unroll
    for (int e=0;e<4;e++){
        int i = base_i + e;
        v[e] = g_logits[b*S_ + i];
        int r = 0;
        #pragma unroll
        for (int c=0;c<8;c++) r += g_rankp[((long long)c*B_ + b)*S_ + i];
        rank[e] = r;
    }
    int flag[4]; int cnt = 0;
    #pragma unroll
    for (int e=0;e<4;e++){ flag[e] = rank[e] < T_; cnt += flag[e]; }
    scn[tid] = cnt; __syncthreads();
    for (int off=1; off<1024; off<<=1){
        int t = 0;
        if (tid >= off) t = scn[tid-off];
        __syncthreads();
        scn[tid] += t;
        __syncthreads();
    }
    int pos = scn[tid] - cnt;
    #pragma unroll
    for (int e=0;e<4;e++){
        int i = base_i + e;
        int p = -1;
        if (flag[e]){ p = pos++; g_sel[b*T_+p] = i; selv[p] = v[e]; }
        g_pos[b*S_ + i] = p;
    }
    __syncthreads();
    float sval = selv[tid];
    red[tid] = sval; __syncthreads();
    for (int off=512; off; off>>=1){ if (tid < off) red[tid] = fmaxf(red[tid], red[tid+off]); __syncthreads(); }
    float mx = red[0]; __syncthreads();
    float ex = __expf(sval - mx);
    red[tid] = ex; __syncthreads();
    for (int off=512; off; off>>=1){ if (tid < off) red[tid] += red[tid+off]; __syncthreads(); }
    g_rw[b*T_ + tid] = ex / red[0];
}

__device__ __forceinline__ float block_sum_256(float v, float* sh){
    #pragma unroll
    for (int o=16;o;o>>=1) v += __shfl_xor_sync(0xffffffffu, v, o);
    if ((threadIdx.x & 31) == 0) sh[threadIdx.x >> 5] = v;
    __syncthreads();
    if (threadIdx.x == 0){ float t=0; for (int w=0;w<8;w++) t += sh[w]; sh[0] = t; }
    __syncthreads();
    float r = sh[0];
    __syncthreads();
    return r;
}

__global__ void __launch_bounds__(256) gather_rms_kernel(const float* __restrict__ x,
                                                         const float* __restrict__ g1){
    __shared__ float sh[8];
    int bt = blockIdx.x;
    int b = bt >> 10;
    int s = g_sel[bt];
    const float* xr = x + ((long long)b*S_ + s) * D_;
    float vals[8]; float ss = 0.f;
    #pragma unroll
    for (int e=0;e<8;e++){ float val = xr[threadIdx.x + e*256]; vals[e] = val; ss += val*val; }
    float tot = block_sum_256(ss, sh);
    float inv = rsqrtf(tot / D_ + 1e-6f);
    long long base = (long long)bt * D_;
    #pragma unroll
    for (int e=0;e<8;e++){
        int d = threadIdx.x + e*256;
        g_h[base+d] = __float2bfloat16(vals[e] * inv * g1[d]);
    }
}

__global__ void __launch_bounds__(256) resid_rms_kernel(const float* __restrict__ g2){
    __shared__ float sh[8];
    long long base = (long long)blockIdx.x * D_;
    float vals[8]; float ss = 0.f;
    #pragma unroll
    for (int e=0;e<8;e++){
        int d = threadIdx.x + e*256;
        float val = g_x1[base+d];
        vals[e] = val; ss += val*val;
    }
    float tot = block_sum_256(ss, sh);
    float inv = rsqrtf(tot / D_ + 1e-6f);
    #pragma unroll
    for (int e=0;e<8;e++){
        int d = threadIdx.x + e*256;
        g_h2[base+d] = __float2bfloat16(vals[e] * inv * g2[d]);
    }
}

__global__ void __launch_bounds__(256) final_copy_kernel(const float* __restrict__ x,
                                                         float* __restrict__ out){
    int bs = blockIdx.x;
    if (g_pos[bs] >= 0) return;
    long long rb = (long long)bs * D_;
    #pragma unroll
    for (int e=0;e<2;e++){
        int i = threadIdx.x + e*256;
        reinterpret_cast<float4*>(out + rb)[i] =
            reinterpret_cast<const float4*>(x + rb)[i];
    }
}

// ---------------- host orchestration ----------------
#define GETP(sym_) ([&]{ void* p_ = nullptr; cudaGetSymbolAddress(&p_, sym_); return p_; }())

extern "C" void kernel_launch(void* const* d_in, const int* in_sizes, int n_in,
                              void* d_out, int out_size)
{
    const float* x     = (const float*)d_in[0];
    const float* freqs = (const float*)d_in[2];
    const float* wr    = (const float*)d_in[3];
    const float* g1    = (const float*)d_in[4];
    const float* wq    = (const float*)d_in[5];
    const float* wk    = (const float*)d_in[6];
    const float* wv    = (const float*)d_in[7];
    const float* wo    = (const float*)d_in[8];
    const float* g2    = (const float*)d_in[9];
    const float* w1    = (const float*)d_in[10];
    const float* w3    = (const float*)d_in[11];
    const float* w2    = (const float*)d_in[12];
    float* out = (float*)d_out;

    static bool init_done = false;
    static cudaStream_t s2;
    static cudaEvent_t ev_fork, ev_qkv, ev_join;
    if (!init_done){
        cudaFuncSetAttribute(gemm3<1>, cudaFuncAttributeMaxDynamicSharedMemorySize, GEMM_SMEM);
        cudaFuncSetAttribute(gemm3<2>, cudaFuncAttributeMaxDynamicSharedMemorySize, GEMM_SMEM);
        cudaFuncSetAttribute(gemm3<4>, cudaFuncAttributeMaxDynamicSharedMemorySize, GEMM_SMEM);
        cudaFuncSetAttribute(gemm3<5>, cudaFuncAttributeMaxDynamicSharedMemorySize, GEMM_SMEM);
        cudaFuncSetAttribute(gemm3<6>, cudaFuncAttributeMaxDynamicSharedMemorySize, GEMM_SMEM);
        cudaFuncSetAttribute(flash_kernel, cudaFuncAttributeMaxDynamicSharedMemorySize, FA_SMEM);
        cudaStreamCreateWithFlags(&s2, cudaStreamNonBlocking);
        cudaEventCreateWithFlags(&ev_fork, cudaEventDisableTiming);
        cudaEventCreateWithFlags(&ev_qkv,  cudaEventDisableTiming);
        cudaEventCreateWithFlags(&ev_join, cudaEventDisableTiming);
        init_done = true;
    }

    __nv_bfloat16* p_wqkv = (__nv_bfloat16*)GETP(g_wqkv);
    __nv_bfloat16* p_wo = (__nv_bfloat16*)GETP(g_wo_b);
    __nv_bfloat16* p_w1 = (__nv_bfloat16*)GETP(g_w1_b);
    __nv_bfloat16* p_w3 = (__nv_bfloat16*)GETP(g_w3_b);
    __nv_bfloat16* p_w2 = (__nv_bfloat16*)GETP(g_w2_b);
    __nv_bfloat16* p_h  = (__nv_bfloat16*)GETP(g_h);
    __nv_bfloat16* p_qb = (__nv_bfloat16*)GETP(g_qb);
    __nv_bfloat16* p_kb = (__nv_bfloat16*)GETP(g_kb);
    __nv_bfloat16* p_vb = (__nv_bfloat16*)GETP(g_vb);
    __nv_bfloat16* p_ob = (__nv_bfloat16*)GETP(g_ob);
    __nv_bfloat16* p_h2 = (__nv_bfloat16*)GETP(g_h2);
    __nv_bfloat16* p_u  = (__nv_bfloat16*)GETP(g_u);
    __nv_bfloat16* p_ac = (__nv_bfloat16*)GETP(g_act);
    float* p_x1 = (float*)GETP(g_x1);

    // fork: SINGLE side stream does ALL weight conversion (qkv first),
    // main stream runs the router chain concurrently.
    cudaEventRecord(ev_fork, 0);
    cudaStreamWaitEvent(s2, ev_fork, 0);
    cvt_qkv_kernel<<<2048, 256, 0, s2>>>(wq, wk, wv);
    cudaEventRecord(ev_qkv, s2);
    cvt_rest_kernel<<<4096, 256, 0, s2>>>(wo, w1, w3, w2);
    cudaEventRecord(ev_join, s2);

    // main chain (independent of weights)
    router_kernel<<<B_*S_/8, 256>>>(x, wr);
    rank_kernel<<<dim3(16, 8, B_), 256>>>();
    compact_kernel<<<B_, 1024>>>();
    gather_rms_kernel<<<M_, 256>>>(x, g1);

    // QKV GEMM needs converted wqkv
    cudaStreamWaitEvent(0, ev_qkv, 0);
    gemm3<4><<<dim3(D_/BN, M_/BM, 3), 256, GEMM_SMEM>>>(p_h, p_wqkv, nullptr,
        D_, D_, D_, D_, 0, (long long)D_*D_, 0, freqs, nullptr, nullptr);

    // fused flash attention -> g_ob [b,t,d] bf16
    flash_kernel<<<dim3(T_/128, B_*H_), 256, FA_SMEM>>>(p_qb, p_kb, p_vb, p_ob);

    // join: wo/w1/w3/w2 must be converted from here on
    cudaStreamWaitEvent(0, ev_join, 0);

    // attn projection + gathered residual: x1 = x[b,sel] + ob@wo
    gemm3<6><<<dim3(D_/BN, M_/BM, 1), 256, GEMM_SMEM>>>(p_ob, p_wo, p_x1,
        D_, D_, D_, D_, 0,0,0, nullptr, nullptr, x);

    // rmsnorm2
    resid_rms_kernel<<<M_, 256>>>(g2);

    // FFN: u = h2@w1 (bf16) ; act = silu(u)*(h2@w3)
    gemm3<2><<<dim3(F_/BN, M_/BM, 1), 256, GEMM_SMEM>>>(p_h2, p_w1, nullptr,
        D_, D_, F_, F_, 0,0,0, nullptr, p_u, nullptr);
    gemm3<1><<<dim3(F_/BN, M_/BM, 1), 256, GEMM_SMEM>>>(p_h2, p_w3, nullptr,
        D_, D_, F_, F_, 0,0,0, p_u, p_ac, nullptr);

    // w2 GEMM with fused final scatter-add
    gemm3<5><<<dim3(D_/BN, M_/BM, 1), 256, GEMM_SMEM>>>(p_ac, p_w2, out,
        F_, F_, D_, D_, 0,0,0, p_x1, nullptr, x);

    // copy non-selected rows
    final_copy_kernel<<<B_*S_, 256>>>(x, out);
}

// round 16
// speedup vs baseline: 1.5349x; 1.0120x over previous
#include <cuda_runtime.h>
#include <cuda_bf16.h>
#include <cstdint>

// Problem dims
#define B_  4
#define S_  4096
#define D_  2048
#define T_  1024
#define H_  16
#define HD_ 128
#define F_  8192
#define M_  (B_*T_)

// ---------------- device scratch ----------------
#define DEVBUF(type, name, count) __device__ __align__(256) type name[count]

DEVBUF(__nv_bfloat16, g_wqkv, 3LL*D_*D_);   // packed [wq|wk|wv]
DEVBUF(__nv_bfloat16, g_wo_b, D_*D_);
DEVBUF(__nv_bfloat16, g_w1_b, D_*F_);
DEVBUF(__nv_bfloat16, g_w3_b, D_*F_);
DEVBUF(__nv_bfloat16, g_w2_b, F_*D_);

DEVBUF(float, g_logits, B_*S_);
DEVBUF(int,   g_rankp,  8LL*B_*S_);
DEVBUF(int,   g_sel,    B_*T_);
DEVBUF(int,   g_pos,    B_*S_);
DEVBUF(float, g_rw,     B_*T_);

DEVBUF(__nv_bfloat16, g_h,   M_*D_);
DEVBUF(__nv_bfloat16, g_qb,  M_*D_);        // [b,h,t,hd] (rope'd)
DEVBUF(__nv_bfloat16, g_kb,  M_*D_);
DEVBUF(__nv_bfloat16, g_vb,  M_*D_);
DEVBUF(__nv_bfloat16, g_ob,  M_*D_);        // attn out [b,t,d] bf16
DEVBUF(float,         g_x1,  M_*D_);        // x_gathered + attn proj
DEVBUF(__nv_bfloat16, g_h2,  M_*D_);
DEVBUF(__nv_bfloat16, g_u,   M_*F_);        // bf16 u
DEVBUF(__nv_bfloat16, g_act, M_*F_);

// ---------------- PTX helpers ----------------
__device__ __forceinline__ uint32_t smem_u32(const void* p){
    uint32_t a;
    asm("{ .reg .u64 t; cvta.to.shared.u64 t, %1; cvt.u32.u64 %0, t; }" : "=r"(a) : "l"(p));
    return a;
}
__device__ __forceinline__ void cpasync16(uint32_t dst, const void* src){
    asm volatile("cp.async.cg.shared.global [%0], [%1], 16;" :: "r"(dst), "l"(src));
}
__device__ __forceinline__ void ldsm_x4(uint32_t* r, uint32_t addr){
    asm volatile("ldmatrix.sync.aligned.m8n8.x4.shared.b16 {%0,%1,%2,%3}, [%4];"
        : "=r"(r[0]), "=r"(r[1]), "=r"(r[2]), "=r"(r[3]) : "r"(addr));
}
__device__ __forceinline__ void ldsm_x4_t(uint32_t* r, uint32_t addr){
    asm volatile("ldmatrix.sync.aligned.m8n8.x4.trans.shared.b16 {%0,%1,%2,%3}, [%4];"
        : "=r"(r[0]), "=r"(r[1]), "=r"(r[2]), "=r"(r[3]) : "r"(addr));
}
__device__ __forceinline__ void mma16816(float* c, const uint32_t* a, uint32_t b0, uint32_t b1){
    asm volatile("mma.sync.aligned.m16n8k16.row.col.f32.bf16.bf16.f32 "
        "{%0,%1,%2,%3}, {%4,%5,%6,%7}, {%8,%9}, {%0,%1,%2,%3};"
        : "+f"(c[0]), "+f"(c[1]), "+f"(c[2]), "+f"(c[3])
        : "r"(a[0]), "r"(a[1]), "r"(a[2]), "r"(a[3]), "r"(b0), "r"(b1));
}
__device__ __forceinline__ uint32_t pack_bf16x2(float lo, float hi){
    __nv_bfloat162 v = __floats2bfloat162_rn(lo, hi);
    return *reinterpret_cast<uint32_t*>(&v);
}

// ---------------- raw mma.sync GEMM (128x128 CTA, 2 CTAs/SM) ----------------
// EPI=1: silu(Ubf)*acc -> bf16; EPI=2: bf16 store
// EPI=4: QKV+RoPE epilogue (z=0 q rope, z=1 k rope, z=2 v plain), Uv=freqs
// EPI=5: fused final: out[b,sel] = x + rw*(x1 + acc); Uv=x1, Xf=x, C=out
// EPI=6: x1 = x_gathered + acc; Xf=x, C=x1

#define BM 128
#define BN 128
#define BK 64
#define STAGE_B 32768
#define GEMM_SMEM (3*STAGE_B)

__device__ __forceinline__ void ldA_128x64(const __nv_bfloat16* g, int ld, uint32_t sbase, int tid){
    #pragma unroll
    for (int i = 0; i < 4; i++){
        int ch = tid + i*256;
        int r = ch >> 3, c = ch & 7;
        cpasync16(sbase + r*128 + (((c ^ (r & 7))) << 4),
                  (const char*)(g + (long long)r*ld) + c*16);
    }
}
__device__ __forceinline__ void ldB_64x128(const __nv_bfloat16* g, int ld, uint32_t sbase, int tid){
    #pragma unroll
    for (int i = 0; i < 4; i++){
        int ch = tid + i*256;
        int r = ch >> 4, c = ch & 15;
        int half = c >> 3, c8 = c & 7;
        cpasync16(sbase + r*256 + half*128 + ((c8 ^ (r & 7)) << 4),
                  (const char*)(g + (long long)r*ld) + c*16);
    }
}

template<int EPI>
__global__ void __launch_bounds__(256, 2) gemm3(
    const __nv_bfloat16* __restrict__ A, const __nv_bfloat16* __restrict__ Bm,
    float* __restrict__ C, int K, int lda, int ldb, int ldc,
    long long sA, long long sB, long long sC,
    const void* __restrict__ Uv, __nv_bfloat16* __restrict__ Obf,
    const float* __restrict__ Xf)
{
    extern __shared__ char smem[];
    uint32_t sb = smem_u32(smem);
    int tid = threadIdx.x, warp = tid >> 5, lane = tid & 31;
    int z = blockIdx.z;
    const __nv_bfloat16* Ab = A + (long long)z*sA + (long long)blockIdx.y*BM*lda;
    const __nv_bfloat16* Bb = Bm + (long long)z*sB;
    float* Cb = C ? C + (long long)z*sC : nullptr;
    __nv_bfloat16* Ob = Obf ? Obf + (long long)z*sC : nullptr;
    const int bn = blockIdx.x*BN;

    int wm = (warp & 3) * 32;
    int wn = (warp >> 2) * 64;

    float acc[2][8][4];
    #pragma unroll
    for (int i=0;i<2;i++)
        #pragma unroll
        for (int j=0;j<8;j++)
            #pragma unroll
            for (int e=0;e<4;e++) acc[i][j][e] = 0.f;

    const int NS = K >> 6;

    auto load_stage = [&](int s){
        uint32_t base = sb + (s % 3)*STAGE_B;
        int k0 = s*BK;
        ldA_128x64(Ab + k0, lda, base, tid);
        ldB_64x128(Bb + (long long)k0*ldb + bn, ldb, base + 16384, tid);
        asm volatile("cp.async.commit_group;" ::: "memory");
    };

    load_stage(0);
    if (NS > 1) load_stage(1);

    int a_row_lo = wm + ((lane >> 3) & 1)*8 + (lane & 7);
    int a_kq     = (lane >> 4) * 8;
    int b0_krow  = ((lane >> 3) & 1)*8 + (lane & 7);
    int b0_ncol  = wn + (lane >> 4)*8;

    for (int s = 0; s < NS; s++){
        if (s + 1 < NS) asm volatile("cp.async.wait_group 1;" ::: "memory");
        else            asm volatile("cp.async.wait_group 0;" ::: "memory");
        __syncthreads();
        // NOTE: loads for s+2 target buffer (s+2)%3 which is free (s uses s%3,
        // s+1 in flight). Next iteration's leading sync (post-wait) guarantees
        // all warps finished stage-s MMAs before stage s+3 loads are issued,
        // so no trailing barrier is needed in this loop.
        if (s + 2 < NS) load_stage(s + 2);

        uint32_t Abase = sb + (s % 3)*STAGE_B;
        uint32_t Bbase = Abase + 16384;

        #pragma unroll
        for (int kk = 0; kk < BK; kk += 16){
            uint32_t af[2][4];
            #pragma unroll
            for (int ii = 0; ii < 2; ii++){
                int mrow = a_row_lo + ii*16;
                int kb = kk + a_kq;
                ldsm_x4(af[ii], Abase + mrow*128 + ((((kb >> 3) ^ (mrow & 7))) << 4));
            }
            uint32_t bfm[4][4];
            #pragma unroll
            for (int jj = 0; jj < 4; jj++){
                int krow = kk + b0_krow;
                int ncol = b0_ncol + jj*16;
                ldsm_x4_t(bfm[jj], Bbase + krow*256 + ((ncol >> 6) & 1)*128
                                 + ((((ncol >> 3) & 7) ^ (krow & 7)) << 4));
            }
            #pragma unroll
            for (int ii = 0; ii < 2; ii++)
                #pragma unroll
                for (int jj = 0; jj < 4; jj++){
                    mma16816(acc[ii][2*jj],   af[ii], bfm[jj][0], bfm[jj][1]);
                    mma16816(acc[ii][2*jj+1], af[ii], bfm[jj][2], bfm[jj][3]);
                }
        }
    }
    __syncthreads();   // protect smem reuse in EPI=4 epilogue

    if (EPI == 4){
        int h = blockIdx.x;
        if (z == 2){
            #pragma unroll
            for (int ii = 0; ii < 2; ii++){
                int r0 = blockIdx.y*BM + wm + ii*16 + (lane >> 2);
                int b = r0 >> 10, t = r0 & (T_-1);
                long long dbase = ((long long)(b*H_ + h)*T_ + t)*HD_;
                #pragma unroll
                for (int j8 = 0; j8 < 8; j8++){
                    int wc = wn + j8*8 + (lane & 3)*2;
                    *reinterpret_cast<uint32_t*>(g_vb + dbase + wc) =
                        pack_bf16x2(acc[ii][j8][0], acc[ii][j8][1]);
                    *reinterpret_cast<uint32_t*>(g_vb + dbase + 8LL*HD_ + wc) =
                        pack_bf16x2(acc[ii][j8][2], acc[ii][j8][3]);
                }
            }
        } else {
            float* sf = reinterpret_cast<float*>(smem);
            #pragma unroll
            for (int ii = 0; ii < 2; ii++){
                int sr = wm + ii*16 + (lane >> 2);
                #pragma unroll
                for (int j8 = 0; j8 < 8; j8++){
                    int sc = wn + j8*8 + (lane & 3)*2;
                    sf[sr*136 + sc]     = acc[ii][j8][0];
                    sf[sr*136 + sc + 1] = acc[ii][j8][1];
                    sf[(sr+8)*136 + sc]     = acc[ii][j8][2];
                    sf[(sr+8)*136 + sc + 1] = acc[ii][j8][3];
                }
            }
            __syncthreads();
            const float* fr = (const float*)Uv;
            __nv_bfloat16* dstp = (z == 0) ? g_qb : g_kb;
            #pragma unroll
            for (int i = 0; i < 32; i++){
                int idx = tid + i*256;
                int row = idx >> 6;
                int d2  = (idx & 63) * 2;
                int r = blockIdx.y*BM + row;
                int b = r >> 10, t = r & (T_-1);
                float v0 = sf[row*136 + d2];
                float v1 = sf[row*136 + d2 + 1];
                float p0 = sf[row*136 + (d2 ^ 64)];
                float p1 = sf[row*136 + (d2 ^ 64) + 1];
                int j0 = d2 & 63;
                float c0 = fr[(t*64 + j0)*2],     s0 = fr[(t*64 + j0)*2 + 1];
                float c1 = fr[(t*64 + j0 + 1)*2], s1 = fr[(t*64 + j0 + 1)*2 + 1];
                float o0, o1;
                if (d2 < 64){ o0 = v0*c0 - p0*s0; o1 = v1*c1 - p1*s1; }
                else        { o0 = p0*s0 + v0*c0; o1 = p1*s1 + v1*c1; }
                long long dst = ((long long)(b*H_ + h)*T_ + t)*HD_ + d2;
                *reinterpret_cast<uint32_t*>(dstp + dst) = pack_bf16x2(o0, o1);
            }
        }
        return;
    }

    #pragma unroll
    for (int ii = 0; ii < 2; ii++){
        int r0 = blockIdx.y*BM + wm + ii*16 + (lane >> 2);
        int selA = 0, selB = 0; float wA = 0.f, wB = 0.f; int bA = 0;
        if (EPI == 5 || EPI == 6){
            bA = r0 >> 10;
            selA = g_sel[r0];
            selB = g_sel[r0 + 8];
            if (EPI == 5){ wA = g_rw[r0]; wB = g_rw[r0 + 8]; }
        }
        #pragma unroll
        for (int j8 = 0; j8 < 8; j8++){
            int c0 = bn + wn + j8*8 + (lane & 3)*2;
            long long i0 = (long long)r0*ldc + c0;
            long long i1 = i0 + 8*(long long)ldc;
            if (EPI == 1){
                const __nv_bfloat16* Ub = (const __nv_bfloat16*)Uv;
                __nv_bfloat162 u0 = *reinterpret_cast<const __nv_bfloat162*>(Ub + i0);
                __nv_bfloat162 u1 = *reinterpret_cast<const __nv_bfloat162*>(Ub + i1);
                float ux = __bfloat162float(u0.x), uy = __bfloat162float(u0.y);
                float uz = __bfloat162float(u1.x), uw = __bfloat162float(u1.y);
                float s0 = __fdividef(ux, 1.f + __expf(-ux)) * acc[ii][j8][0];
                float s1 = __fdividef(uy, 1.f + __expf(-uy)) * acc[ii][j8][1];
                float s2 = __fdividef(uz, 1.f + __expf(-uz)) * acc[ii][j8][2];
                float s3 = __fdividef(uw, 1.f + __expf(-uw)) * acc[ii][j8][3];
                *reinterpret_cast<uint32_t*>(Ob + i0) = pack_bf16x2(s0, s1);
                *reinterpret_cast<uint32_t*>(Ob + i1) = pack_bf16x2(s2, s3);
            } else if (EPI == 2){
                *reinterpret_cast<uint32_t*>(Ob + i0) = pack_bf16x2(acc[ii][j8][0], acc[ii][j8][1]);
                *reinterpret_cast<uint32_t*>(Ob + i1) = pack_bf16x2(acc[ii][j8][2], acc[ii][j8][3]);
            } else if (EPI == 6){
                long long o0 = ((long long)bA*S_ + selA)*D_ + c0;
                long long o1 = ((long long)bA*S_ + selB)*D_ + c0;
                float2 x0 = *reinterpret_cast<const float2*>(Xf + o0);
                float2 x1v = *reinterpret_cast<const float2*>(Xf + o1);
                *reinterpret_cast<float2*>(Cb + i0) = make_float2(acc[ii][j8][0] + x0.x, acc[ii][j8][1] + x0.y);
                *reinterpret_cast<float2*>(Cb + i1) = make_float2(acc[ii][j8][2] + x1v.x, acc[ii][j8][3] + x1v.y);
            } else { // EPI == 5
                const float* X1 = (const float*)Uv;
                float2 a0 = *reinterpret_cast<const float2*>(X1 + i0);
                float2 a1 = *reinterpret_cast<const float2*>(X1 + i1);
                long long o0 = ((long long)bA*S_ + selA)*D_ + c0;
                long long o1 = ((long long)bA*S_ + selB)*D_ + c0;
                float2 x0 = *reinterpret_cast<const float2*>(Xf + o0);
                float2 x1v = *reinterpret_cast<const float2*>(Xf + o1);
                *reinterpret_cast<float2*>(Cb + o0) =
                    make_float2(x0.x + wA*(a0.x + acc[ii][j8][0]), x0.y + wA*(a0.y + acc[ii][j8][1]));
                *reinterpret_cast<float2*>(Cb + o1) =
                    make_float2(x1v.x + wB*(a1.x + acc[ii][j8][2]), x1v.y + wB*(a1.y + acc[ii][j8][3]));
            }
        }
    }
}

// ---------------- fused flash attention: double-buffered, 2 CTAs/SM ----------------
#define FA_STAGE 32768
#define FA_SMEM (32768 + 2*FA_STAGE)

__global__ void __launch_bounds__(256, 2) flash_kernel(
    const __nv_bfloat16* __restrict__ Q, const __nv_bfloat16* __restrict__ K,
    const __nv_bfloat16* __restrict__ V, __nv_bfloat16* __restrict__ Ob)
{
    extern __shared__ char smem[];
    uint32_t sq = smem_u32(smem);
    int tid = threadIdx.x, warp = tid >> 5, lane = tid & 31;
    int qt = blockIdx.x;
    int bh = blockIdx.y;
    int h = bh & (H_-1), b = bh >> 4;
    const __nv_bfloat16* Qb = Q + ((long long)bh*T_ + qt*128)*HD_;
    const __nv_bfloat16* Kb = K + (long long)bh*T_*HD_;
    const __nv_bfloat16* Vb = V + (long long)bh*T_*HD_;

    #pragma unroll
    for (int i = 0; i < 8; i++){
        int ch = tid + i*256;
        int r = ch >> 4, c = ch & 15;
        cpasync16(sq + r*256 + (c >> 3)*128 + (((c & 7) ^ (r & 7)) << 4),
                  (const char*)(Qb + (long long)r*HD_) + c*16);
    }
    auto load_kv = [&](int s){
        uint32_t base = sq + 32768 + (s & 1)*FA_STAGE;
        const __nv_bfloat16* Kt = Kb + (long long)s*64*HD_;
        const __nv_bfloat16* Vt = Vb + (long long)s*64*HD_;
        #pragma unroll
        for (int i = 0; i < 4; i++){
            int ch = tid + i*256;
            int r = ch >> 4, c = ch & 15;
            uint32_t off = r*256 + (c >> 3)*128 + (((c & 7) ^ (r & 7)) << 4);
            cpasync16(base + off,         (const char*)(Kt + (long long)r*HD_) + c*16);
            cpasync16(base + 16384 + off, (const char*)(Vt + (long long)r*HD_) + c*16);
        }
        asm volatile("cp.async.commit_group;" ::: "memory");
    };
    load_kv(0);
    load_kv(1);

    const int qr0 = warp*16;
    float o[16][4];
    #pragma unroll
    for (int j=0;j<16;j++)
        #pragma unroll
        for (int e=0;e<4;e++) o[j][e] = 0.f;
    float m0 = -1e30f, m1 = -1e30f, l0 = 0.f, l1 = 0.f;
    const float sc = 0.08838834764831845f;

    int a_row  = qr0 + ((lane >> 3) & 1)*8 + (lane & 7);
    int a_kq   = (lane >> 4) * 8;
    int b_row  = (lane >> 4)*8 + (lane & 7);
    int b_kq   = ((lane >> 3) & 1) * 8;
    int v_krow = ((lane >> 3) & 1)*8 + (lane & 7);
    int v_ncol = (lane >> 4) * 8;

    for (int s = 0; s < 16; s++){
        if (s + 1 < 16) asm volatile("cp.async.wait_group 1;" ::: "memory");
        else            asm volatile("cp.async.wait_group 0;" ::: "memory");
        __syncthreads();

        uint32_t Kbase = sq + 32768 + (s & 1)*FA_STAGE;
        uint32_t Vbase = Kbase + 16384;

        float sv[8][4];
        #pragma unroll
        for (int j=0;j<8;j++)
            #pragma unroll
            for (int e=0;e<4;e++) sv[j][e] = 0.f;

        #pragma unroll
        for (int kk = 0; kk < 8; kk++){
            uint32_t af[4];
            int cA = (kk*16 + a_kq) >> 3;
            ldsm_x4(af, sq + a_row*256 + (cA >> 3)*128 + (((cA & 7) ^ (a_row & 7)) << 4));
            #pragma unroll
            for (int jj = 0; jj < 4; jj++){
                uint32_t bfm[4];
                int nrow = jj*16 + b_row;
                int cB = (kk*16 + b_kq) >> 3;
                ldsm_x4(bfm, Kbase + nrow*256 + (cB >> 3)*128 + (((cB & 7) ^ (nrow & 7)) << 4));
                mma16816(sv[2*jj],   af, bfm[0], bfm[1]);
                mma16816(sv[2*jj+1], af, bfm[2], bfm[3]);
            }
        }

        float rm0 = -1e30f, rm1 = -1e30f;
        #pragma unroll
        for (int j=0;j<8;j++){
            sv[j][0] *= sc; sv[j][1] *= sc; sv[j][2] *= sc; sv[j][3] *= sc;
            rm0 = fmaxf(rm0, fmaxf(sv[j][0], sv[j][1]));
            rm1 = fmaxf(rm1, fmaxf(sv[j][2], sv[j][3]));
        }
        rm0 = fmaxf(rm0, __shfl_xor_sync(0xffffffffu, rm0, 1));
        rm0 = fmaxf(rm0, __shfl_xor_sync(0xffffffffu, rm0, 2));
        rm1 = fmaxf(rm1, __shfl_xor_sync(0xffffffffu, rm1, 1));
        rm1 = fmaxf(rm1, __shfl_xor_sync(0xffffffffu, rm1, 2));
        float mn0 = fmaxf(m0, rm0), mn1 = fmaxf(m1, rm1);
        float rs0 = 0.f, rs1 = 0.f;
        #pragma unroll
        for (int j=0;j<8;j++){
            sv[j][0] = __expf(sv[j][0] - mn0);
            sv[j][1] = __expf(sv[j][1] - mn0);
            sv[j][2] = __expf(sv[j][2] - mn1);
            sv[j][3] = __expf(sv[j][3] - mn1);
            rs0 += sv[j][0] + sv[j][1];
            rs1 += sv[j][2] + sv[j][3];
        }
        rs0 += __shfl_xor_sync(0xffffffffu, rs0, 1);
        rs0 += __shfl_xor_sync(0xffffffffu, rs0, 2);
        rs1 += __shfl_xor_sync(0xffffffffu, rs1, 1);
        rs1 += __shfl_xor_sync(0xffffffffu, rs1, 2);
        float c0 = __expf(m0 - mn0), c1 = __expf(m1 - mn1);
        l0 = l0*c0 + rs0;  l1 = l1*c1 + rs1;
        m0 = mn0;  m1 = mn1;
        #pragma unroll
        for (int j=0;j<16;j++){
            o[j][0] *= c0; o[j][1] *= c0; o[j][2] *= c1; o[j][3] *= c1;
        }

        #pragma unroll
        for (int k2 = 0; k2 < 4; k2++){
            uint32_t pa[4];
            pa[0] = pack_bf16x2(sv[2*k2][0],   sv[2*k2][1]);
            pa[1] = pack_bf16x2(sv[2*k2][2],   sv[2*k2][3]);
            pa[2] = pack_bf16x2(sv[2*k2+1][0], sv[2*k2+1][1]);
            pa[3] = pack_bf16x2(sv[2*k2+1][2], sv[2*k2+1][3]);
            int krow = k2*16 + v_krow;
            #pragma unroll
            for (int jj = 0; jj < 8; jj++){
                uint32_t bv[4];
                int ncol = jj*16 + v_ncol;
                ldsm_x4_t(bv, Vbase + krow*256 + ((ncol >> 6) & 1)*128
                              + ((((ncol >> 3) & 7) ^ (krow & 7)) << 4));
                mma16816(o[2*jj],   pa, bv[0], bv[1]);
                mma16816(o[2*jj+1], pa, bv[2], bv[3]);
            }
        }
        __syncthreads();           // required: next load targets the buffer just read
        if (s + 2 < 16) load_kv(s + 2);
    }

    float il0 = __frcp_rn(l0), il1 = __frcp_rn(l1);
    int t0 = qt*128 + qr0 + (lane >> 2);
    long long base0 = ((long long)b*T_ + t0)*D_ + h*HD_;
    long long base1 = base0 + 8LL*D_;
    #pragma unroll
    for (int j=0;j<16;j++){
        int col = j*8 + (lane & 3)*2;
        *reinterpret_cast<uint32_t*>(Ob + base0 + col) = pack_bf16x2(o[j][0]*il0, o[j][1]*il0);
        *reinterpret_cast<uint32_t*>(Ob + base1 + col) = pack_bf16x2(o[j][2]*il1, o[j][3]*il1);
    }
}

// ---------------- elementwise / reduction kernels ----------------

__global__ void cvt_qkv_kernel(const float* __restrict__ wq, const float* __restrict__ wk,
                               const float* __restrict__ wv){
    const int SEG = 1 << 20;
    for (int i = blockIdx.x*blockDim.x + threadIdx.x; i < 3*SEG; i += gridDim.x*blockDim.x){
        int seg = i >> 20;
        long long off = i & (SEG-1);
        const float* src = (seg == 0) ? wq : (seg == 1) ? wk : wv;
        __nv_bfloat16* dst = g_wqkv + (long long)seg*D_*D_;
        float4 v = reinterpret_cast<const float4*>(src)[off];
        __nv_bfloat162* o = reinterpret_cast<__nv_bfloat162*>(dst) + off*2;
        o[0] = __floats2bfloat162_rn(v.x, v.y);
        o[1] = __floats2bfloat162_rn(v.z, v.w);
    }
}

__global__ void cvt_rest_kernel(const float* __restrict__ wo, const float* __restrict__ w1,
                                const float* __restrict__ w3, const float* __restrict__ w2){
    const int SEG = 1 << 20;
    for (long long i = blockIdx.x*(long long)blockDim.x + threadIdx.x;
         i < 13LL*SEG; i += (long long)gridDim.x*blockDim.x){
        int seg = (int)(i >> 20);
        const float* src; __nv_bfloat16* dst; long long off;
        if (seg < 1){        off = i;            src = wo; dst = g_wo_b; }
        else if (seg < 5){   off = i - 1LL*SEG;  src = w1; dst = g_w1_b; }
        else if (seg < 9){   off = i - 5LL*SEG;  src = w3; dst = g_w3_b; }
        else{                off = i - 9LL*SEG;  src = w2; dst = g_w2_b; }
        float4 v = reinterpret_cast<const float4*>(src)[off];
        __nv_bfloat162* o = reinterpret_cast<__nv_bfloat162*>(dst) + off*2;
        o[0] = __floats2bfloat162_rn(v.x, v.y);
        o[1] = __floats2bfloat162_rn(v.z, v.w);
    }
}

__global__ void __launch_bounds__(256) router_kernel(const float* __restrict__ x,
                                                     const float* __restrict__ wr){
    int row = blockIdx.x*8 + (threadIdx.x >> 5);
    int lane = threadIdx.x & 31;
    const float* xr = x + (long long)row * D_;
    float s = 0.f;
    #pragma unroll 8
    for (int i = lane; i < D_; i += 32) s += xr[i] * wr[i];
    #pragma unroll
    for (int o=16;o;o>>=1) s += __shfl_xor_sync(0xffffffffu, s, o);
    if (!lane) g_logits[row] = s;
}

// chunked exact rank counting: grid (16, 8, B), 512-element chunks
__global__ void __launch_bounds__(256) rank_kernel(){
    __shared__ float sv[512];
    int b = blockIdx.z, c = blockIdx.y;
    int i = blockIdx.x*256 + threadIdx.x;
    for (int j = threadIdx.x; j < 512; j += 256) sv[j] = g_logits[b*S_ + c*512 + j];
    __syncthreads();
    float v = g_logits[b*S_ + i];
    int base = c*512;
    int rank = 0;
    #pragma unroll 8
    for (int j = 0; j < 512; j++){
        float vj = sv[j];
        rank += (vj > v) || (vj == v && (base + j) < i);
    }
    g_rankp[((long long)c*B_ + b)*S_ + i] = rank;
}

// compaction + router softmax
__global__ void __launch_bounds__(1024) compact_kernel(){
    __shared__ int   scn[1024];
    __shared__ float selv[T_];
    __shared__ float red[1024];
    int b = blockIdx.x, tid = threadIdx.x;
    int base_i = tid*4;
    float v[4]; int rank[4];
    #pragma unroll
    for (int e=0;e<4;e++){
        int i = base_i + e;
        v[e] = g_logits[b*S_ + i];
        int r = 0;
        #pragma unroll
        for (int c=0;c<8;c++) r += g_rankp[((long long)c*B_ + b)*S_ + i];
        rank[e] = r;
    }
    int flag[4]; int cnt = 0;
    #pragma unroll
    for (int e=0;e<4;e++){ flag[e] = rank[e] < T_; cnt += flag[e]; }
    scn[tid] = cnt; __syncthreads();
    for (int off=1; off<1024; off<<=1){
        int t = 0;
        if (tid >= off) t = scn[tid-off];
        __syncthreads();
        scn[tid] += t;
        __syncthreads();
    }
    int pos = scn[tid] - cnt;
    #pragma unroll
    for (int e=0;e<4;e++){
        int i = base_i + e;
        int p = -1;
        if (flag[e]){ p = pos++; g_sel[b*T_+p] = i; selv[p] = v[e]; }
        g_pos[b*S_ + i] = p;
    }
    __syncthreads();
    float sval = selv[tid];
    red[tid] = sval; __syncthreads();
    for (int off=512; off; off>>=1){ if (tid < off) red[tid] = fmaxf(red[tid], red[tid+off]); __syncthreads(); }
    float mx = red[0]; __syncthreads();
    float ex = __expf(sval - mx);
    red[tid] = ex; __syncthreads();
    for (int off=512; off; off>>=1){ if (tid < off) red[tid] += red[tid+off]; __syncthreads(); }
    g_rw[b*T_ + tid] = ex / red[0];
}

__device__ __forceinline__ float block_sum_256(float v, float* sh){
    #pragma unroll
    for (int o=16;o;o>>=1) v += __shfl_xor_sync(0xffffffffu, v, o);
    if ((threadIdx.x & 31) == 0) sh[threadIdx.x >> 5] = v;
    __syncthreads();
    if (threadIdx.x == 0){ float t=0; for (int w=0;w<8;w++) t += sh[w]; sh[0] = t; }
    __syncthreads();
    float r = sh[0];
    __syncthreads();
    return r;
}

__global__ void __launch_bounds__(256) gather_rms_kernel(const float* __restrict__ x,
                                                         const float* __restrict__ g1){
    __shared__ float sh[8];
    int bt = blockIdx.x;
    int b = bt >> 10;
    int s = g_sel[bt];
    const float* xr = x + ((long long)b*S_ + s) * D_;
    float vals[8]; float ss = 0.f;
    #pragma unroll
    for (int e=0;e<8;e++){ float val = xr[threadIdx.x + e*256]; vals[e] = val; ss += val*val; }
    float tot = block_sum_256(ss, sh);
    float inv = rsqrtf(tot / D_ + 1e-6f);
    long long base = (long long)bt * D_;
    #pragma unroll
    for (int e=0;e<8;e++){
        int d = threadIdx.x + e*256;
        g_h[base+d] = __float2bfloat16(vals[e] * inv * g1[d]);
    }
}

__global__ void __launch_bounds__(256) resid_rms_kernel(const float* __restrict__ g2){
    __shared__ float sh[8];
    long long base = (long long)blockIdx.x * D_;
    float vals[8]; float ss = 0.f;
    #pragma unroll
    for (int e=0;e<8;e++){
        int d = threadIdx.x + e*256;
        float val = g_x1[base+d];
        vals[e] = val; ss += val*val;
    }
    float tot = block_sum_256(ss, sh);
    float inv = rsqrtf(tot / D_ + 1e-6f);
    #pragma unroll
    for (int e=0;e<8;e++){
        int d = threadIdx.x + e*256;
        g_h2[base+d] = __float2bfloat16(vals[e] * inv * g2[d]);
    }
}

__global__ void __launch_bounds__(256) final_copy_kernel(const float* __restrict__ x,
                                                         float* __restrict__ out){
    int bs = blockIdx.x;
    if (g_pos[bs] >= 0) return;
    long long rb = (long long)bs * D_;
    #pragma unroll
    for (int e=0;e<2;e++){
        int i = threadIdx.x + e*256;
        reinterpret_cast<float4*>(out + rb)[i] =
            reinterpret_cast<const float4*>(x + rb)[i];
    }
}

// ---------------- host orchestration ----------------
#define GETP(sym_) ([&]{ void* p_ = nullptr; cudaGetSymbolAddress(&p_, sym_); return p_; }())

extern "C" void kernel_launch(void* const* d_in, const int* in_sizes, int n_in,
                              void* d_out, int out_size)
{
    const float* x     = (const float*)d_in[0];
    const float* freqs = (const float*)d_in[2];
    const float* wr    = (const float*)d_in[3];
    const float* g1    = (const float*)d_in[4];
    const float* wq    = (const float*)d_in[5];
    const float* wk    = (const float*)d_in[6];
    const float* wv    = (const float*)d_in[7];
    const float* wo    = (const float*)d_in[8];
    const float* g2    = (const float*)d_in[9];
    const float* w1    = (const float*)d_in[10];
    const float* w3    = (const float*)d_in[11];
    const float* w2    = (const float*)d_in[12];
    float* out = (float*)d_out;

    static bool init_done = false;
    static cudaStream_t s2;
    static cudaEvent_t ev_fork, ev_qkv, ev_join;
    if (!init_done){
        cudaFuncSetAttribute(gemm3<1>, cudaFuncAttributeMaxDynamicSharedMemorySize, GEMM_SMEM);
        cudaFuncSetAttribute(gemm3<2>, cudaFuncAttributeMaxDynamicSharedMemorySize, GEMM_SMEM);
        cudaFuncSetAttribute(gemm3<4>, cudaFuncAttributeMaxDynamicSharedMemorySize, GEMM_SMEM);
        cudaFuncSetAttribute(gemm3<5>, cudaFuncAttributeMaxDynamicSharedMemorySize, GEMM_SMEM);
        cudaFuncSetAttribute(gemm3<6>, cudaFuncAttributeMaxDynamicSharedMemorySize, GEMM_SMEM);
        cudaFuncSetAttribute(flash_kernel, cudaFuncAttributeMaxDynamicSharedMemorySize, FA_SMEM);
        cudaStreamCreateWithFlags(&s2, cudaStreamNonBlocking);
        cudaEventCreateWithFlags(&ev_fork, cudaEventDisableTiming);
        cudaEventCreateWithFlags(&ev_qkv,  cudaEventDisableTiming);
        cudaEventCreateWithFlags(&ev_join, cudaEventDisableTiming);
        init_done = true;
    }

    __nv_bfloat16* p_wqkv = (__nv_bfloat16*)GETP(g_wqkv);
    __nv_bfloat16* p_wo = (__nv_bfloat16*)GETP(g_wo_b);
    __nv_bfloat16* p_w1 = (__nv_bfloat16*)GETP(g_w1_b);
    __nv_bfloat16* p_w3 = (__nv_bfloat16*)GETP(g_w3_b);
    __nv_bfloat16* p_w2 = (__nv_bfloat16*)GETP(g_w2_b);
    __nv_bfloat16* p_h  = (__nv_bfloat16*)GETP(g_h);
    __nv_bfloat16* p_qb = (__nv_bfloat16*)GETP(g_qb);
    __nv_bfloat16* p_kb = (__nv_bfloat16*)GETP(g_kb);
    __nv_bfloat16* p_vb = (__nv_bfloat16*)GETP(g_vb);
    __nv_bfloat16* p_ob = (__nv_bfloat16*)GETP(g_ob);
    __nv_bfloat16* p_h2 = (__nv_bfloat16*)GETP(g_h2);
    __nv_bfloat16* p_u  = (__nv_bfloat16*)GETP(g_u);
    __nv_bfloat16* p_ac = (__nv_bfloat16*)GETP(g_act);
    float* p_x1 = (float*)GETP(g_x1);

    // fork: SINGLE side stream does ALL weight conversion (qkv first),
    // main stream runs the router chain concurrently.
    cudaEventRecord(ev_fork, 0);
    cudaStreamWaitEvent(s2, ev_fork, 0);
    cvt_qkv_kernel<<<2048, 256, 0, s2>>>(wq, wk, wv);
    cudaEventRecord(ev_qkv, s2);
    cvt_rest_kernel<<<8192, 256, 0, s2>>>(wo, w1, w3, w2);
    cudaEventRecord(ev_join, s2);

    // main chain (independent of weights)
    router_kernel<<<B_*S_/8, 256>>>(x, wr);
    rank_kernel<<<dim3(16, 8, B_), 256>>>();
    compact_kernel<<<B_, 1024>>>();
    gather_rms_kernel<<<M_, 256>>>(x, g1);

    // QKV GEMM needs converted wqkv
    cudaStreamWaitEvent(0, ev_qkv, 0);
    gemm3<4><<<dim3(D_/BN, M_/BM, 3), 256, GEMM_SMEM>>>(p_h, p_wqkv, nullptr,
        D_, D_, D_, D_, 0, (long long)D_*D_, 0, freqs, nullptr, nullptr);

    // fused flash attention -> g_ob [b,t,d] bf16
    flash_kernel<<<dim3(T_/128, B_*H_), 256, FA_SMEM>>>(p_qb, p_kb, p_vb, p_ob);

    // join: wo/w1/w3/w2 must be converted from here on
    cudaStreamWaitEvent(0, ev_join, 0);

    // attn projection + gathered residual: x1 = x[b,sel] + ob@wo
    gemm3<6><<<dim3(D_/BN, M_/BM, 1), 256, GEMM_SMEM>>>(p_ob, p_wo, p_x1,
        D_, D_, D_, D_, 0,0,0, nullptr, nullptr, x);

    // rmsnorm2
    resid_rms_kernel<<<M_, 256>>>(g2);

    // FFN: u = h2@w1 (bf16) ; act = silu(u)*(h2@w3)
    gemm3<2><<<dim3(F_/BN, M_/BM, 1), 256, GEMM_SMEM>>>(p_h2, p_w1, nullptr,
        D_, D_, F_, F_, 0,0,0, nullptr, p_u, nullptr);
    gemm3<1><<<dim3(F_/BN, M_/BM, 1), 256, GEMM_SMEM>>>(p_h2, p_w3, nullptr,
        D_, D_, F_, F_, 0,0,0, p_u, p_ac, nullptr);

    // w2 GEMM with fused final scatter-add
    gemm3<5><<<dim3(D_/BN, M_/BM, 1), 256, GEMM_SMEM>>>(p_ac, p_w2, out,
        F_, F_, D_, D_, 0,0,0, p_x1, nullptr, x);

    // copy non-selected rows
    final_copy_kernel<<<B_*S_, 256>>>(x, out);
}

// round 17
// speedup vs baseline: 1.5510x; 1.0105x over previous
#include <cuda_runtime.h>
#include <cuda_bf16.h>
#include <cstdint>

// Problem dims
#define B_  4
#define S_  4096
#define D_  2048
#define T_  1024
#define H_  16
#define HD_ 128
#define F_  8192
#define M_  (B_*T_)

// ---------------- device scratch ----------------
#define DEVBUF(type, name, count) __device__ __align__(256) type name[count]

DEVBUF(__nv_bfloat16, g_wqkv, 3LL*D_*D_);   // packed [wq|wk|wv]
DEVBUF(__nv_bfloat16, g_wo_b, D_*D_);
DEVBUF(__nv_bfloat16, g_w13, 2LL*D_*F_);    // interleaved [w1|w3] columns
DEVBUF(__nv_bfloat16, g_w2_b, F_*D_);

DEVBUF(float, g_logits, B_*S_);
DEVBUF(int,   g_rankp,  8LL*B_*S_);
DEVBUF(int,   g_sel,    B_*T_);
DEVBUF(int,   g_pos,    B_*S_);
DEVBUF(float, g_rw,     B_*T_);

DEVBUF(__nv_bfloat16, g_h,   M_*D_);
DEVBUF(__nv_bfloat16, g_qb,  M_*D_);        // [b,h,t,hd] (rope'd)
DEVBUF(__nv_bfloat16, g_kb,  M_*D_);
DEVBUF(__nv_bfloat16, g_vb,  M_*D_);
DEVBUF(__nv_bfloat16, g_ob,  M_*D_);        // attn out [b,t,d] bf16
DEVBUF(float,         g_x1,  M_*D_);        // x_gathered + attn proj
DEVBUF(__nv_bfloat16, g_h2,  M_*D_);
DEVBUF(__nv_bfloat16, g_act, M_*F_);

// ---------------- PTX helpers ----------------
__device__ __forceinline__ uint32_t smem_u32(const void* p){
    uint32_t a;
    asm("{ .reg .u64 t; cvta.to.shared.u64 t, %1; cvt.u32.u64 %0, t; }" : "=r"(a) : "l"(p));
    return a;
}
__device__ __forceinline__ void cpasync16(uint32_t dst, const void* src){
    asm volatile("cp.async.cg.shared.global [%0], [%1], 16;" :: "r"(dst), "l"(src));
}
__device__ __forceinline__ void ldsm_x4(uint32_t* r, uint32_t addr){
    asm volatile("ldmatrix.sync.aligned.m8n8.x4.shared.b16 {%0,%1,%2,%3}, [%4];"
        : "=r"(r[0]), "=r"(r[1]), "=r"(r[2]), "=r"(r[3]) : "r"(addr));
}
__device__ __forceinline__ void ldsm_x4_t(uint32_t* r, uint32_t addr){
    asm volatile("ldmatrix.sync.aligned.m8n8.x4.trans.shared.b16 {%0,%1,%2,%3}, [%4];"
        : "=r"(r[0]), "=r"(r[1]), "=r"(r[2]), "=r"(r[3]) : "r"(addr));
}
__device__ __forceinline__ void mma16816(float* c, const uint32_t* a, uint32_t b0, uint32_t b1){
    asm volatile("mma.sync.aligned.m16n8k16.row.col.f32.bf16.bf16.f32 "
        "{%0,%1,%2,%3}, {%4,%5,%6,%7}, {%8,%9}, {%0,%1,%2,%3};"
        : "+f"(c[0]), "+f"(c[1]), "+f"(c[2]), "+f"(c[3])
        : "r"(a[0]), "r"(a[1]), "r"(a[2]), "r"(a[3]), "r"(b0), "r"(b1));
}
__device__ __forceinline__ uint32_t pack_bf16x2(float lo, float hi){
    __nv_bfloat162 v = __floats2bfloat162_rn(lo, hi);
    return *reinterpret_cast<uint32_t*>(&v);
}

// ---------------- raw mma.sync GEMM (128x128 CTA, 2 CTAs/SM) ----------------
// EPI=2: bf16 store
// EPI=4: QKV+RoPE epilogue (z=0 q rope, z=1 k rope, z=2 v plain), Uv=freqs
// EPI=5: fused final: out[b,sel] = x + rw*(x1 + acc); Uv=x1, Xf=x, C=out
// EPI=6: x1 = x_gathered + acc; Xf=x, C=x1
// EPI=7: interleaved SwiGLU: even col=u, odd col=g -> silu(u)*g bf16 at [row, col/2]

#define BM 128
#define BN 128
#define BK 64
#define STAGE_B 32768
#define GEMM_SMEM (3*STAGE_B)

__device__ __forceinline__ void ldA_128x64(const __nv_bfloat16* g, int ld, uint32_t sbase, int tid){
    #pragma unroll
    for (int i = 0; i < 4; i++){
        int ch = tid + i*256;
        int r = ch >> 3, c = ch & 7;
        cpasync16(sbase + r*128 + (((c ^ (r & 7))) << 4),
                  (const char*)(g + (long long)r*ld) + c*16);
    }
}
__device__ __forceinline__ void ldB_64x128(const __nv_bfloat16* g, int ld, uint32_t sbase, int tid){
    #pragma unroll
    for (int i = 0; i < 4; i++){
        int ch = tid + i*256;
        int r = ch >> 4, c = ch & 15;
        int half = c >> 3, c8 = c & 7;
        cpasync16(sbase + r*256 + half*128 + ((c8 ^ (r & 7)) << 4),
                  (const char*)(g + (long long)r*ld) + c*16);
    }
}

template<int EPI>
__global__ void __launch_bounds__(256, 2) gemm3(
    const __nv_bfloat16* __restrict__ A, const __nv_bfloat16* __restrict__ Bm,
    float* __restrict__ C, int K, int lda, int ldb, int ldc,
    long long sA, long long sB, long long sC,
    const void* __restrict__ Uv, __nv_bfloat16* __restrict__ Obf,
    const float* __restrict__ Xf)
{
    extern __shared__ char smem[];
    uint32_t sb = smem_u32(smem);
    int tid = threadIdx.x, warp = tid >> 5, lane = tid & 31;
    int z = blockIdx.z;
    const __nv_bfloat16* Ab = A + (long long)z*sA + (long long)blockIdx.y*BM*lda;
    const __nv_bfloat16* Bb = Bm + (long long)z*sB;
    float* Cb = C ? C + (long long)z*sC : nullptr;
    __nv_bfloat16* Ob = Obf ? Obf + (long long)z*sC : nullptr;
    const int bn = blockIdx.x*BN;

    int wm = (warp & 3) * 32;
    int wn = (warp >> 2) * 64;

    float acc[2][8][4];
    #pragma unroll
    for (int i=0;i<2;i++)
        #pragma unroll
        for (int j=0;j<8;j++)
            #pragma unroll
            for (int e=0;e<4;e++) acc[i][j][e] = 0.f;

    const int NS = K >> 6;

    auto load_stage = [&](int s){
        uint32_t base = sb + (s % 3)*STAGE_B;
        int k0 = s*BK;
        ldA_128x64(Ab + k0, lda, base, tid);
        ldB_64x128(Bb + (long long)k0*ldb + bn, ldb, base + 16384, tid);
        asm volatile("cp.async.commit_group;" ::: "memory");
    };

    load_stage(0);
    if (NS > 1) load_stage(1);

    int a_row_lo = wm + ((lane >> 3) & 1)*8 + (lane & 7);
    int a_kq     = (lane >> 4) * 8;
    int b0_krow  = ((lane >> 3) & 1)*8 + (lane & 7);
    int b0_ncol  = wn + (lane >> 4)*8;

    for (int s = 0; s < NS; s++){
        if (s + 1 < NS) asm volatile("cp.async.wait_group 1;" ::: "memory");
        else            asm volatile("cp.async.wait_group 0;" ::: "memory");
        __syncthreads();
        if (s + 2 < NS) load_stage(s + 2);

        uint32_t Abase = sb + (s % 3)*STAGE_B;
        uint32_t Bbase = Abase + 16384;

        #pragma unroll
        for (int kk = 0; kk < BK; kk += 16){
            uint32_t af[2][4];
            #pragma unroll
            for (int ii = 0; ii < 2; ii++){
                int mrow = a_row_lo + ii*16;
                int kb = kk + a_kq;
                ldsm_x4(af[ii], Abase + mrow*128 + ((((kb >> 3) ^ (mrow & 7))) << 4));
            }
            uint32_t bfm[4][4];
            #pragma unroll
            for (int jj = 0; jj < 4; jj++){
                int krow = kk + b0_krow;
                int ncol = b0_ncol + jj*16;
                ldsm_x4_t(bfm[jj], Bbase + krow*256 + ((ncol >> 6) & 1)*128
                                 + ((((ncol >> 3) & 7) ^ (krow & 7)) << 4));
            }
            #pragma unroll
            for (int ii = 0; ii < 2; ii++)
                #pragma unroll
                for (int jj = 0; jj < 4; jj++){
                    mma16816(acc[ii][2*jj],   af[ii], bfm[jj][0], bfm[jj][1]);
                    mma16816(acc[ii][2*jj+1], af[ii], bfm[jj][2], bfm[jj][3]);
                }
        }
    }
    __syncthreads();   // protect smem reuse in EPI=4 epilogue

    if (EPI == 4){
        int h = blockIdx.x;
        if (z == 2){
            #pragma unroll
            for (int ii = 0; ii < 2; ii++){
                int r0 = blockIdx.y*BM + wm + ii*16 + (lane >> 2);
                int b = r0 >> 10, t = r0 & (T_-1);
                long long dbase = ((long long)(b*H_ + h)*T_ + t)*HD_;
                #pragma unroll
                for (int j8 = 0; j8 < 8; j8++){
                    int wc = wn + j8*8 + (lane & 3)*2;
                    *reinterpret_cast<uint32_t*>(g_vb + dbase + wc) =
                        pack_bf16x2(acc[ii][j8][0], acc[ii][j8][1]);
                    *reinterpret_cast<uint32_t*>(g_vb + dbase + 8LL*HD_ + wc) =
                        pack_bf16x2(acc[ii][j8][2], acc[ii][j8][3]);
                }
            }
        } else {
            float* sf = reinterpret_cast<float*>(smem);
            #pragma unroll
            for (int ii = 0; ii < 2; ii++){
                int sr = wm + ii*16 + (lane >> 2);
                #pragma unroll
                for (int j8 = 0; j8 < 8; j8++){
                    int sc = wn + j8*8 + (lane & 3)*2;
                    sf[sr*136 + sc]     = acc[ii][j8][0];
                    sf[sr*136 + sc + 1] = acc[ii][j8][1];
                    sf[(sr+8)*136 + sc]     = acc[ii][j8][2];
                    sf[(sr+8)*136 + sc + 1] = acc[ii][j8][3];
                }
            }
            __syncthreads();
            const float* fr = (const float*)Uv;
            __nv_bfloat16* dstp = (z == 0) ? g_qb : g_kb;
            #pragma unroll
            for (int i = 0; i < 32; i++){
                int idx = tid + i*256;
                int row = idx >> 6;
                int d2  = (idx & 63) * 2;
                int r = blockIdx.y*BM + row;
                int b = r >> 10, t = r & (T_-1);
                float v0 = sf[row*136 + d2];
                float v1 = sf[row*136 + d2 + 1];
                float p0 = sf[row*136 + (d2 ^ 64)];
                float p1 = sf[row*136 + (d2 ^ 64) + 1];
                int j0 = d2 & 63;
                float c0 = fr[(t*64 + j0)*2],     s0 = fr[(t*64 + j0)*2 + 1];
                float c1 = fr[(t*64 + j0 + 1)*2], s1 = fr[(t*64 + j0 + 1)*2 + 1];
                float o0, o1;
                if (d2 < 64){ o0 = v0*c0 - p0*s0; o1 = v1*c1 - p1*s1; }
                else        { o0 = p0*s0 + v0*c0; o1 = p1*s1 + v1*c1; }
                long long dst = ((long long)(b*H_ + h)*T_ + t)*HD_ + d2;
                *reinterpret_cast<uint32_t*>(dstp + dst) = pack_bf16x2(o0, o1);
            }
        }
        return;
    }

    #pragma unroll
    for (int ii = 0; ii < 2; ii++){
        int r0 = blockIdx.y*BM + wm + ii*16 + (lane >> 2);
        int selA = 0, selB = 0; float wA = 0.f, wB = 0.f; int bA = 0;
        if (EPI == 5 || EPI == 6){
            bA = r0 >> 10;
            selA = g_sel[r0];
            selB = g_sel[r0 + 8];
            if (EPI == 5){ wA = g_rw[r0]; wB = g_rw[r0 + 8]; }
        }
        #pragma unroll
        for (int j8 = 0; j8 < 8; j8++){
            int c0 = bn + wn + j8*8 + (lane & 3)*2;
            long long i0 = (long long)r0*ldc + c0;
            long long i1 = i0 + 8*(long long)ldc;
            if (EPI == 2){
                *reinterpret_cast<uint32_t*>(Ob + i0) = pack_bf16x2(acc[ii][j8][0], acc[ii][j8][1]);
                *reinterpret_cast<uint32_t*>(Ob + i1) = pack_bf16x2(acc[ii][j8][2], acc[ii][j8][3]);
            } else if (EPI == 7){
                // even col = u, odd col = g (interleaved w13); act col = c0/2
                long long a0 = (long long)r0*F_ + (c0 >> 1);
                long long a1 = a0 + 8LL*F_;
                float u0 = acc[ii][j8][0], gg0 = acc[ii][j8][1];
                float u1 = acc[ii][j8][2], gg1 = acc[ii][j8][3];
                Ob[a0] = __float2bfloat16(__fdividef(u0, 1.f + __expf(-u0)) * gg0);
                Ob[a1] = __float2bfloat16(__fdividef(u1, 1.f + __expf(-u1)) * gg1);
            } else if (EPI == 6){
                long long o0 = ((long long)bA*S_ + selA)*D_ + c0;
                long long o1 = ((long long)bA*S_ + selB)*D_ + c0;
                float2 x0 = *reinterpret_cast<const float2*>(Xf + o0);
                float2 x1v = *reinterpret_cast<const float2*>(Xf + o1);
                *reinterpret_cast<float2*>(Cb + i0) = make_float2(acc[ii][j8][0] + x0.x, acc[ii][j8][1] + x0.y);
                *reinterpret_cast<float2*>(Cb + i1) = make_float2(acc[ii][j8][2] + x1v.x, acc[ii][j8][3] + x1v.y);
            } else { // EPI == 5
                const float* X1 = (const float*)Uv;
                float2 a0 = *reinterpret_cast<const float2*>(X1 + i0);
                float2 a1 = *reinterpret_cast<const float2*>(X1 + i1);
                long long o0 = ((long long)bA*S_ + selA)*D_ + c0;
                long long o1 = ((long long)bA*S_ + selB)*D_ + c0;
                float2 x0 = *reinterpret_cast<const float2*>(Xf + o0);
                float2 x1v = *reinterpret_cast<const float2*>(Xf + o1);
                *reinterpret_cast<float2*>(Cb + o0) =
                    make_float2(x0.x + wA*(a0.x + acc[ii][j8][0]), x0.y + wA*(a0.y + acc[ii][j8][1]));
                *reinterpret_cast<float2*>(Cb + o1) =
                    make_float2(x1v.x + wB*(a1.x + acc[ii][j8][2]), x1v.y + wB*(a1.y + acc[ii][j8][3]));
            }
        }
    }
}

// ---------------- fused flash attention: double-buffered, 2 CTAs/SM ----------------
#define FA_STAGE 32768
#define FA_SMEM (32768 + 2*FA_STAGE)

__global__ void __launch_bounds__(256, 2) flash_kernel(
    const __nv_bfloat16* __restrict__ Q, const __nv_bfloat16* __restrict__ K,
    const __nv_bfloat16* __restrict__ V, __nv_bfloat16* __restrict__ Ob)
{
    extern __shared__ char smem[];
    uint32_t sq = smem_u32(smem);
    int tid = threadIdx.x, warp = tid >> 5, lane = tid & 31;
    int qt = blockIdx.x;
    int bh = blockIdx.y;
    int h = bh & (H_-1), b = bh >> 4;
    const __nv_bfloat16* Qb = Q + ((long long)bh*T_ + qt*128)*HD_;
    const __nv_bfloat16* Kb = K + (long long)bh*T_*HD_;
    const __nv_bfloat16* Vb = V + (long long)bh*T_*HD_;

    #pragma unroll
    for (int i = 0; i < 8; i++){
        int ch = tid + i*256;
        int r = ch >> 4, c = ch & 15;
        cpasync16(sq + r*256 + (c >> 3)*128 + (((c & 7) ^ (r & 7)) << 4),
                  (const char*)(Qb + (long long)r*HD_) + c*16);
    }
    auto load_kv = [&](int s){
        uint32_t base = sq + 32768 + (s & 1)*FA_STAGE;
        const __nv_bfloat16* Kt = Kb + (long long)s*64*HD_;
        const __nv_bfloat16* Vt = Vb + (long long)s*64*HD_;
        #pragma unroll
        for (int i = 0; i < 4; i++){
            int ch = tid + i*256;
            int r = ch >> 4, c = ch & 15;
            uint32_t off = r*256 + (c >> 3)*128 + (((c & 7) ^ (r & 7)) << 4);
            cpasync16(base + off,         (const char*)(Kt + (long long)r*HD_) + c*16);
            cpasync16(base + 16384 + off, (const char*)(Vt + (long long)r*HD_) + c*16);
        }
        asm volatile("cp.async.commit_group;" ::: "memory");
    };
    load_kv(0);
    load_kv(1);

    const int qr0 = warp*16;
    float o[16][4];
    #pragma unroll
    for (int j=0;j<16;j++)
        #pragma unroll
        for (int e=0;e<4;e++) o[j][e] = 0.f;
    float m0 = -1e30f, m1 = -1e30f, l0 = 0.f, l1 = 0.f;
    const float sc = 0.08838834764831845f;

    int a_row  = qr0 + ((lane >> 3) & 1)*8 + (lane & 7);
    int a_kq   = (lane >> 4) * 8;
    int b_row  = (lane >> 4)*8 + (lane & 7);
    int b_kq   = ((lane >> 3) & 1) * 8;
    int v_krow = ((lane >> 3) & 1)*8 + (lane & 7);
    int v_ncol = (lane >> 4) * 8;

    for (int s = 0; s < 16; s++){
        if (s + 1 < 16) asm volatile("cp.async.wait_group 1;" ::: "memory");
        else            asm volatile("cp.async.wait_group 0;" ::: "memory");
        __syncthreads();

        uint32_t Kbase = sq + 32768 + (s & 1)*FA_STAGE;
        uint32_t Vbase = Kbase + 16384;

        float sv[8][4];
        #pragma unroll
        for (int j=0;j<8;j++)
            #pragma unroll
            for (int e=0;e<4;e++) sv[j][e] = 0.f;

        #pragma unroll
        for (int kk = 0; kk < 8; kk++){
            uint32_t af[4];
            int cA = (kk*16 + a_kq) >> 3;
            ldsm_x4(af, sq + a_row*256 + (cA >> 3)*128 + (((cA & 7) ^ (a_row & 7)) << 4));
            #pragma unroll
            for (int jj = 0; jj < 4; jj++){
                uint32_t bfm[4];
                int nrow = jj*16 + b_row;
                int cB = (kk*16 + b_kq) >> 3;
                ldsm_x4(bfm, Kbase + nrow*256 + (cB >> 3)*128 + (((cB & 7) ^ (nrow & 7)) << 4));
                mma16816(sv[2*jj],   af, bfm[0], bfm[1]);
                mma16816(sv[2*jj+1], af, bfm[2], bfm[3]);
            }
        }

        float rm0 = -1e30f, rm1 = -1e30f;
        #pragma unroll
        for (int j=0;j<8;j++){
            sv[j][0] *= sc; sv[j][1] *= sc; sv[j][2] *= sc; sv[j][3] *= sc;
            rm0 = fmaxf(rm0, fmaxf(sv[j][0], sv[j][1]));
            rm1 = fmaxf(rm1, fmaxf(sv[j][2], sv[j][3]));
        }
        rm0 = fmaxf(rm0, __shfl_xor_sync(0xffffffffu, rm0, 1));
        rm0 = fmaxf(rm0, __shfl_xor_sync(0xffffffffu, rm0, 2));
        rm1 = fmaxf(rm1, __shfl_xor_sync(0xffffffffu, rm1, 1));
        rm1 = fmaxf(rm1, __shfl_xor_sync(0xffffffffu, rm1, 2));
        float mn0 = fmaxf(m0, rm0), mn1 = fmaxf(m1, rm1);
        float rs0 = 0.f, rs1 = 0.f;
        #pragma unroll
        for (int j=0;j<8;j++){
            sv[j][0] = __expf(sv[j][0] - mn0);
            sv[j][1] = __expf(sv[j][1] - mn0);
            sv[j][2] = __expf(sv[j][2] - mn1);
            sv[j][3] = __expf(sv[j][3] - mn1);
            rs0 += sv[j][0] + sv[j][1];
            rs1 += sv[j][2] + sv[j][3];
        }
        rs0 += __shfl_xor_sync(0xffffffffu, rs0, 1);
        rs0 += __shfl_xor_sync(0xffffffffu, rs0, 2);
        rs1 += __shfl_xor_sync(0xffffffffu, rs1, 1);
        rs1 += __shfl_xor_sync(0xffffffffu, rs1, 2);
        float c0 = __expf(m0 - mn0), c1 = __expf(m1 - mn1);
        l0 = l0*c0 + rs0;  l1 = l1*c1 + rs1;
        m0 = mn0;  m1 = mn1;
        #pragma unroll
        for (int j=0;j<16;j++){
            o[j][0] *= c0; o[j][1] *= c0; o[j][2] *= c1; o[j][3] *= c1;
        }

        #pragma unroll
        for (int k2 = 0; k2 < 4; k2++){
            uint32_t pa[4];
            pa[0] = pack_bf16x2(sv[2*k2][0],   sv[2*k2][1]);
            pa[1] = pack_bf16x2(sv[2*k2][2],   sv[2*k2][3]);
            pa[2] = pack_bf16x2(sv[2*k2+1][0], sv[2*k2+1][1]);
            pa[3] = pack_bf16x2(sv[2*k2+1][2], sv[2*k2+1][3]);
            int krow = k2*16 + v_krow;
            #pragma unroll
            for (int jj = 0; jj < 8; jj++){
                uint32_t bv[4];
                int ncol = jj*16 + v_ncol;
                ldsm_x4_t(bv, Vbase + krow*256 + ((ncol >> 6) & 1)*128
                              + ((((ncol >> 3) & 7) ^ (krow & 7)) << 4));
                mma16816(o[2*jj],   pa, bv[0], bv[1]);
                mma16816(o[2*jj+1], pa, bv[2], bv[3]);
            }
        }
        __syncthreads();           // required: next load targets the buffer just read
        if (s + 2 < 16) load_kv(s + 2);
    }

    float il0 = __frcp_rn(l0), il1 = __frcp_rn(l1);
    int t0 = qt*128 + qr0 + (lane >> 2);
    long long base0 = ((long long)b*T_ + t0)*D_ + h*HD_;
    long long base1 = base0 + 8LL*D_;
    #pragma unroll
    for (int j=0;j<16;j++){
        int col = j*8 + (lane & 3)*2;
        *reinterpret_cast<uint32_t*>(Ob + base0 + col) = pack_bf16x2(o[j][0]*il0, o[j][1]*il0);
        *reinterpret_cast<uint32_t*>(Ob + base1 + col) = pack_bf16x2(o[j][2]*il1, o[j][3]*il1);
    }
}

// ---------------- elementwise / reduction kernels ----------------

__global__ void cvt_qkv_kernel(const float* __restrict__ wq, const float* __restrict__ wk,
                               const float* __restrict__ wv){
    const int SEG = 1 << 20;
    for (int i = blockIdx.x*blockDim.x + threadIdx.x; i < 3*SEG; i += gridDim.x*blockDim.x){
        int seg = i >> 20;
        long long off = i & (SEG-1);
        const float* src = (seg == 0) ? wq : (seg == 1) ? wk : wv;
        __nv_bfloat16* dst = g_wqkv + (long long)seg*D_*D_;
        float4 v = reinterpret_cast<const float4*>(src)[off];
        __nv_bfloat162* o = reinterpret_cast<__nv_bfloat162*>(dst) + off*2;
        o[0] = __floats2bfloat162_rn(v.x, v.y);
        o[1] = __floats2bfloat162_rn(v.z, v.w);
    }
}

// wo + w2 plain convert; w1/w3 interleaved into g_w13
__global__ void cvt_rest_kernel(const float* __restrict__ wo, const float* __restrict__ w1,
                                const float* __restrict__ w3, const float* __restrict__ w2){
    const int SEG = 1 << 20;
    // total work: wo (1 seg) + w2 (4 segs) + w13 interleave (4 segs of float4-pairs)
    for (long long i = blockIdx.x*(long long)blockDim.x + threadIdx.x;
         i < 9LL*SEG; i += (long long)gridDim.x*blockDim.x){
        int seg = (int)(i >> 20);
        if (seg < 1){
            long long off = i;
            float4 v = reinterpret_cast<const float4*>(wo)[off];
            __nv_bfloat162* o = reinterpret_cast<__nv_bfloat162*>(g_wo_b) + off*2;
            o[0] = __floats2bfloat162_rn(v.x, v.y);
            o[1] = __floats2bfloat162_rn(v.z, v.w);
        } else if (seg < 5){
            long long off = i - 1LL*SEG;
            float4 v = reinterpret_cast<const float4*>(w2)[off];
            __nv_bfloat162* o = reinterpret_cast<__nv_bfloat162*>(g_w2_b) + off*2;
            o[0] = __floats2bfloat162_rn(v.x, v.y);
            o[1] = __floats2bfloat162_rn(v.z, v.w);
        } else {
            // interleave: off indexes float4 of w1/w3 (4M total = 4 segs)
            long long off = i - 5LL*SEG;
            float4 a = reinterpret_cast<const float4*>(w1)[off];
            float4 g = reinterpret_cast<const float4*>(w3)[off];
            __nv_bfloat162 r[4];
            r[0] = __floats2bfloat162_rn(a.x, g.x);
            r[1] = __floats2bfloat162_rn(a.y, g.y);
            r[2] = __floats2bfloat162_rn(a.z, g.z);
            r[3] = __floats2bfloat162_rn(a.w, g.w);
            reinterpret_cast<uint4*>(g_w13)[off] = *reinterpret_cast<uint4*>(r);
        }
    }
}

__global__ void __launch_bounds__(256) router_kernel(const float* __restrict__ x,
                                                     const float* __restrict__ wr){
    int row = blockIdx.x*8 + (threadIdx.x >> 5);
    int lane = threadIdx.x & 31;
    const float* xr = x + (long long)row * D_;
    float s = 0.f;
    #pragma unroll 8
    for (int i = lane; i < D_; i += 32) s += xr[i] * wr[i];
    #pragma unroll
    for (int o=16;o;o>>=1) s += __shfl_xor_sync(0xffffffffu, s, o);
    if (!lane) g_logits[row] = s;
}

// chunked exact rank counting: grid (16, 8, B), 512-element chunks
__global__ void __launch_bounds__(256) rank_kernel(){
    __shared__ float sv[512];
    int b = blockIdx.z, c = blockIdx.y;
    int i = blockIdx.x*256 + threadIdx.x;
    for (int j = threadIdx.x; j < 512; j += 256) sv[j] = g_logits[b*S_ + c*512 + j];
    __syncthreads();
    float v = g_logits[b*S_ + i];
    int base = c*512;
    int rank = 0;
    #pragma unroll 8
    for (int j = 0; j < 512; j++){
        float vj = sv[j];
        rank += (vj > v) || (vj == v && (base + j) < i);
    }
    g_rankp[((long long)c*B_ + b)*S_ + i] = rank;
}

// compaction + router softmax
__global__ void __launch_bounds__(1024) compact_kernel(){
    __shared__ int   scn[1024];
    __shared__ float selv[T_];
    __shared__ float red[1024];
    int b = blockIdx.x, tid = threadIdx.x;
    int base_i = tid*4;
    float v[4]; int rank[4];
    #pragma unroll
    for (int e=0;e<4;e++){
        int i = base_i + e;
        v[e] = g_logits[b*S_ + i];
        int r = 0;
        #pragma unroll
        for (int c=0;c<8;c++) r += g_rankp[((long long)c*B_ + b)*S_ + i];
        rank[e] = r;
    }
    int flag[4]; int cnt = 0;
    #pragma unroll
    for (int e=0;e<4;e++){ flag[e] = rank[e] < T_; cnt += flag[e]; }
    scn[tid] = cnt; __syncthreads();
    for (int off=1; off<1024; off<<=1){
        int t = 0;
        if (tid >= off) t = scn[tid-off];
        __syncthreads();
        scn[tid] += t;
        __syncthreads();
    }
    int pos = scn[tid] - cnt;
    #pragma unroll
    for (int e=0;e<4;e++){
        int i = base_i + e;
        int p = -1;
        if (flag[e]){ p = pos++; g_sel[b*T_+p] = i; selv[p] = v[e]; }
        g_pos[b*S_ + i] = p;
    }
    __syncthreads();
    float sval = selv[tid];
    red[tid] = sval; __syncthreads();
    for (int off=512; off; off>>=1){ if (tid < off) red[tid] = fmaxf(red[tid], red[tid+off]); __syncthreads(); }
    float mx = red[0]; __syncthreads();
    float ex = __expf(sval - mx);
    red[tid] = ex; __syncthreads();
    for (int off=512; off; off>>=1){ if (tid < off) red[tid] += red[tid+off]; __syncthreads(); }
    g_rw[b*T_ + tid] = ex / red[0];
}

__device__ __forceinline__ float block_sum_256(float v, float* sh){
    #pragma unroll
    for (int o=16;o;o>>=1) v += __shfl_xor_sync(0xffffffffu, v, o);
    if ((threadIdx.x & 31) == 0) sh[threadIdx.x >> 5] = v;
    __syncthreads();
    if (threadIdx.x == 0){ float t=0; for (int w=0;w<8;w++) t += sh[w]; sh[0] = t; }
    __syncthreads();
    float r = sh[0];
    __syncthreads();
    return r;
}

__global__ void __launch_bounds__(256) gather_rms_kernel(const float* __restrict__ x,
                                                         const float* __restrict__ g1){
    __shared__ float sh[8];
    int bt = blockIdx.x;
    int b = bt >> 10;
    int s = g_sel[bt];
    const float* xr = x + ((long long)b*S_ + s) * D_;
    float vals[8]; float ss = 0.f;
    #pragma unroll
    for (int e=0;e<8;e++){ float val = xr[threadIdx.x + e*256]; vals[e] = val; ss += val*val; }
    float tot = block_sum_256(ss, sh);
    float inv = rsqrtf(tot / D_ + 1e-6f);
    long long base = (long long)bt * D_;
    #pragma unroll
    for (int e=0;e<8;e++){
        int d = threadIdx.x + e*256;
        g_h[base+d] = __float2bfloat16(vals[e] * inv * g1[d]);
    }
}

__global__ void __launch_bounds__(256) resid_rms_kernel(const float* __restrict__ g2){
    __shared__ float sh[8];
    long long base = (long long)blockIdx.x * D_;
    float vals[8]; float ss = 0.f;
    #pragma unroll
    for (int e=0;e<8;e++){
        int d = threadIdx.x + e*256;
        float val = g_x1[base+d];
        vals[e] = val; ss += val*val;
    }
    float tot = block_sum_256(ss, sh);
    float inv = rsqrtf(tot / D_ + 1e-6f);
    #pragma unroll
    for (int e=0;e<8;e++){
        int d = threadIdx.x + e*256;
        g_h2[base+d] = __float2bfloat16(vals[e] * inv * g2[d]);
    }
}

__global__ void __launch_bounds__(256) final_copy_kernel(const float* __restrict__ x,
                                                         float* __restrict__ out){
    int bs = blockIdx.x;
    if (g_pos[bs] >= 0) return;
    long long rb = (long long)bs * D_;
    #pragma unroll
    for (int e=0;e<2;e++){
        int i = threadIdx.x + e*256;
        reinterpret_cast<float4*>(out + rb)[i] =
            reinterpret_cast<const float4*>(x + rb)[i];
    }
}

// ---------------- host orchestration ----------------
#define GETP(sym_) ([&]{ void* p_ = nullptr; cudaGetSymbolAddress(&p_, sym_); return p_; }())

extern "C" void kernel_launch(void* const* d_in, const int* in_sizes, int n_in,
                              void* d_out, int out_size)
{
    const float* x     = (const float*)d_in[0];
    const float* freqs = (const float*)d_in[2];
    const float* wr    = (const float*)d_in[3];
    const float* g1    = (const float*)d_in[4];
    const float* wq    = (const float*)d_in[5];
    const float* wk    = (const float*)d_in[6];
    const float* wv    = (const float*)d_in[7];
    const float* wo    = (const float*)d_in[8];
    const float* g2    = (const float*)d_in[9];
    const float* w1    = (const float*)d_in[10];
    const float* w3    = (const float*)d_in[11];
    const float* w2    = (const float*)d_in[12];
    float* out = (float*)d_out;

    static bool init_done = false;
    static cudaStream_t s2;
    static cudaEvent_t ev_fork, ev_qkv, ev_join;
    if (!init_done){
        cudaFuncSetAttribute(gemm3<2>, cudaFuncAttributeMaxDynamicSharedMemorySize, GEMM_SMEM);
        cudaFuncSetAttribute(gemm3<4>, cudaFuncAttributeMaxDynamicSharedMemorySize, GEMM_SMEM);
        cudaFuncSetAttribute(gemm3<5>, cudaFuncAttributeMaxDynamicSharedMemorySize, GEMM_SMEM);
        cudaFuncSetAttribute(gemm3<6>, cudaFuncAttributeMaxDynamicSharedMemorySize, GEMM_SMEM);
        cudaFuncSetAttribute(gemm3<7>, cudaFuncAttributeMaxDynamicSharedMemorySize, GEMM_SMEM);
        cudaFuncSetAttribute(flash_kernel, cudaFuncAttributeMaxDynamicSharedMemorySize, FA_SMEM);
        cudaStreamCreateWithFlags(&s2, cudaStreamNonBlocking);
        cudaEventCreateWithFlags(&ev_fork, cudaEventDisableTiming);
        cudaEventCreateWithFlags(&ev_qkv,  cudaEventDisableTiming);
        cudaEventCreateWithFlags(&ev_join, cudaEventDisableTiming);
        init_done = true;
    }

    __nv_bfloat16* p_wqkv = (__nv_bfloat16*)GETP(g_wqkv);
    __nv_bfloat16* p_wo = (__nv_bfloat16*)GETP(g_wo_b);
    __nv_bfloat16* p_w13 = (__nv_bfloat16*)GETP(g_w13);
    __nv_bfloat16* p_w2 = (__nv_bfloat16*)GETP(g_w2_b);
    __nv_bfloat16* p_h  = (__nv_bfloat16*)GETP(g_h);
    __nv_bfloat16* p_qb = (__nv_bfloat16*)GETP(g_qb);
    __nv_bfloat16* p_kb = (__nv_bfloat16*)GETP(g_kb);
    __nv_bfloat16* p_vb = (__nv_bfloat16*)GETP(g_vb);
    __nv_bfloat16* p_ob = (__nv_bfloat16*)GETP(g_ob);
    __nv_bfloat16* p_h2 = (__nv_bfloat16*)GETP(g_h2);
    __nv_bfloat16* p_ac = (__nv_bfloat16*)GETP(g_act);
    float* p_x1 = (float*)GETP(g_x1);

    // fork: SINGLE side stream does ALL weight conversion (qkv first)
    cudaEventRecord(ev_fork, 0);
    cudaStreamWaitEvent(s2, ev_fork, 0);
    cvt_qkv_kernel<<<2048, 256, 0, s2>>>(wq, wk, wv);
    cudaEventRecord(ev_qkv, s2);
    cvt_rest_kernel<<<8192, 256, 0, s2>>>(wo, w1, w3, w2);
    cudaEventRecord(ev_join, s2);

    // main chain (independent of weights)
    router_kernel<<<B_*S_/8, 256>>>(x, wr);
    rank_kernel<<<dim3(16, 8, B_), 256>>>();
    compact_kernel<<<B_, 1024>>>();
    gather_rms_kernel<<<M_, 256>>>(x, g1);

    // QKV GEMM needs converted wqkv
    cudaStreamWaitEvent(0, ev_qkv, 0);
    gemm3<4><<<dim3(D_/BN, M_/BM, 3), 256, GEMM_SMEM>>>(p_h, p_wqkv, nullptr,
        D_, D_, D_, D_, 0, (long long)D_*D_, 0, freqs, nullptr, nullptr);

    // fused flash attention -> g_ob [b,t,d] bf16
    flash_kernel<<<dim3(T_/128, B_*H_), 256, FA_SMEM>>>(p_qb, p_kb, p_vb, p_ob);

    // join: wo/w13/w2 must be converted from here on
    cudaStreamWaitEvent(0, ev_join, 0);

    // attn projection + gathered residual: x1 = x[b,sel] + ob@wo
    gemm3<6><<<dim3(D_/BN, M_/BM, 1), 256, GEMM_SMEM>>>(p_ob, p_wo, p_x1,
        D_, D_, D_, D_, 0,0,0, nullptr, nullptr, x);

    // rmsnorm2
    resid_rms_kernel<<<M_, 256>>>(g2);

    // FFN: fused interleaved SwiGLU GEMM (N = 2F), act = silu(u)*g in registers
    gemm3<7><<<dim3(2*F_/BN, M_/BM, 1), 256, GEMM_SMEM>>>(p_h2, p_w13, nullptr,
        D_, D_, 2*F_, 2*F_, 0,0,0, nullptr, p_ac, nullptr);

    // w2 GEMM with fused final scatter-add
    gemm3<5><<<dim3(D_/BN, M_/BM, 1), 256, GEMM_SMEM>>>(p_ac, p_w2, out,
        F_, F_, D_, D_, 0,0,0, p_x1, nullptr, x);

    // copy non-selected rows
    final_copy_kernel<<<B_*S_, 256>>>(x, out);
}